// round 4
// baseline (speedup 1.0000x reference)
#include <cuda_runtime.h>
#include <math.h>

// BN scale: 1/sqrt(1 + 1e-5)
#define BNS 0.9999950000374997f

// Fixed problem geometry (derived from the dataset; runtime dims are read
// from in_sizes but scratch is statically sized to these maxima).
#define DD      200
#define NTOT_MX 50006
#define H_MX    100000
#define NE_MX   600000
#define B_MX    2048
#define NR_MX   2048
#define CPITCH  1408      // EP row pitch (1400 cols padded to 128B multiple)
#define FEATK   39600     // 200 * 198

// ---------------- static device scratch (no runtime allocation) ----------
__device__ __align__(128) float g_T[200 * 200];
__device__ __align__(128) float g_U[1200 * 200];
__device__ __align__(128) float g_comb[200 * CPITCH];
__device__ __align__(128) float g_RW[(size_t)NR_MX * 200];
__device__ __align__(128) float g_outR[(size_t)NR_MX * 200];
__device__ __align__(128) float g_EP[(size_t)NTOT_MX * CPITCH];
__device__ __align__(128) float g_hembW[(size_t)H_MX * 200];
__device__ __align__(128) float g_agg[(size_t)NTOT_MX * 200];
__device__ __align__(128) float g_outE[(size_t)NTOT_MX * 200];
__device__ __align__(128) float g_Y[(size_t)B_MX * FEATK];
__device__ __align__(128) float g_FCACC[(size_t)B_MX * 200];

// ---------------- generic tiled SGEMM: C = alpha * A(MxK) @ B(KxN) -------
// BM=BN=128, BK=8, 256 threads, 8x8 microtile. Split-K via blockIdx.z
// (kChunk must be a multiple of 8; K must be a multiple of 8).
template <bool ATOMIC>
__global__ void __launch_bounds__(256) sgemm_k(
    const float* __restrict__ A, const float* __restrict__ B,
    float* __restrict__ C, int M, int Ncols, int K,
    int lda, int ldb, int ldc, float alpha, int kChunk)
{
    __shared__ float As[8][128];
    __shared__ float Bs[8][128];

    const int tid = threadIdx.x;
    const int tx = tid & 15;
    const int ty = tid >> 4;
    const int m0 = blockIdx.y * 128;
    const int n0 = blockIdx.x * 128;

    int kBegin = blockIdx.z * kChunk;
    int kEnd = kBegin + kChunk;
    if (kEnd > K) kEnd = K;

    const int aRow = tid >> 1;
    const int aK4  = (tid & 1) << 2;
    const int bRow = tid >> 5;
    const int bCol = (tid & 31) << 2;

    float acc[8][8];
#pragma unroll
    for (int i = 0; i < 8; i++)
#pragma unroll
        for (int j = 0; j < 8; j++) acc[i][j] = 0.f;

    for (int k0 = kBegin; k0 < kEnd; k0 += 8) {
        float4 av = make_float4(0.f, 0.f, 0.f, 0.f);
        if (m0 + aRow < M)
            av = *(const float4*)(A + (size_t)(m0 + aRow) * lda + (k0 + aK4));
        As[aK4 + 0][aRow] = av.x;
        As[aK4 + 1][aRow] = av.y;
        As[aK4 + 2][aRow] = av.z;
        As[aK4 + 3][aRow] = av.w;

        float4 bv = make_float4(0.f, 0.f, 0.f, 0.f);
        if (n0 + bCol < Ncols)
            bv = *(const float4*)(B + (size_t)(k0 + bRow) * ldb + (n0 + bCol));
        *(float4*)&Bs[bRow][bCol] = bv;

        __syncthreads();
#pragma unroll
        for (int kk = 0; kk < 8; kk++) {
            float ar[8], br[8];
#pragma unroll
            for (int i = 0; i < 8; i++) ar[i] = As[kk][ty * 8 + i];
#pragma unroll
            for (int j = 0; j < 8; j++) br[j] = Bs[kk][tx * 8 + j];
#pragma unroll
            for (int i = 0; i < 8; i++)
#pragma unroll
                for (int j = 0; j < 8; j++)
                    acc[i][j] = fmaf(ar[i], br[j], acc[i][j]);
        }
        __syncthreads();
    }

#pragma unroll
    for (int i = 0; i < 8; i++) {
        int m = m0 + ty * 8 + i;
        if (m >= M) continue;
        if (ATOMIC) {
#pragma unroll
            for (int j = 0; j < 8; j++) {
                int n = n0 + tx * 8 + j;
                if (n < Ncols)
                    atomicAdd(C + (size_t)m * ldc + n, alpha * acc[i][j]);
            }
        } else {
#pragma unroll
            for (int jj = 0; jj < 8; jj += 4) {
                int n = n0 + tx * 8 + jj;
                if (n < Ncols) {
                    float4 v = make_float4(alpha * acc[i][jj + 0],
                                           alpha * acc[i][jj + 1],
                                           alpha * acc[i][jj + 2],
                                           alpha * acc[i][jj + 3]);
                    *(float4*)(C + (size_t)m * ldc + n) = v;
                }
            }
        }
    }
}

// ---------------- build fused weight comb (200 x 1400) -------------------
// comb[i, k*200+j] = 0.5 * pos_k[i] * U[k*200+i, j]   (k = 0..5)
// comb[i, 1200+j]  = w_addpos[200+i, j]
__global__ void build_comb_k(const float* __restrict__ E,
                             const float* __restrict__ w_addpos, int ent)
{
    int idx = blockIdx.x * 256 + threadIdx.x;
    if (idx >= 200 * 1400) return;
    int i = idx / 1400;
    int c = idx - i * 1400;
    float v;
    if (c < 1200) {
        int k = c / 200;
        int j = c - k * 200;
        v = 0.5f * E[(size_t)(ent + k) * DD + i] *
            g_U[(size_t)(k * 200 + i) * 200 + j];
    } else {
        v = w_addpos[(size_t)(200 + i) * 200 + (c - 1200)];
    }
    g_comb[(size_t)i * CPITCH + c] = v;
}

// ---------------- hembW[h] = RW[he0] + sum_k EP[he_{k+1}, k*200 : +200] --
__global__ void hembw_k(const int* __restrict__ he, int H)
{
    int t = blockIdx.x * 256 + threadIdx.x;
    int h = t / 50;
    int c = t - h * 50;
    if (h >= H) return;
    const int* row = he + (size_t)h * 7;
    int r = row[0];
    float4 acc = *(const float4*)(g_RW + (size_t)r * 200 + c * 4);
#pragma unroll
    for (int k = 0; k < 6; k++) {
        int e = row[1 + k];
        float4 v = *(const float4*)(g_EP + (size_t)e * CPITCH + k * 200 + c * 4);
        acc.x += v.x; acc.y += v.y; acc.z += v.z; acc.w += v.w;
    }
    *(float4*)(g_hembW + (size_t)h * 200 + c * 4) = acc;
}

// ---------------- per-edge scatter: agg[seg] += hembW[et] + EW[gidx] -----
__global__ void edge_k(const int* __restrict__ ei,
                       const int* __restrict__ et, int NEdge)
{
    int t = blockIdx.x * 256 + threadIdx.x;
    int e = t / 50;
    int c = t - e * 50;
    if (e >= NEdge) return;
    int seg  = ei[e];          // edge_index[0][e] : segment target
    int gidx = ei[NEdge + e];  // edge_index[1][e] : gathered E row
    int h    = et[e];
    float4 a = *(const float4*)(g_hembW + (size_t)h * 200 + c * 4);
    float4 b = *(const float4*)(g_EP + (size_t)gidx * CPITCH + 1200 + c * 4);
    float* p = g_agg + (size_t)seg * 200 + c * 4;
    atomicAdd(p + 0, a.x + b.x);
    atomicAdd(p + 1, a.y + b.y);
    atomicAdd(p + 2, a.z + b.z);
    atomicAdd(p + 3, a.w + b.w);
}

// ---------------- outE = tanh(bn(0.5*agg + 0.5*E)) -----------------------
__global__ void oute_k(const float* __restrict__ E,
                       const float* __restrict__ g,
                       const float* __restrict__ bb, int Ntot)
{
    int t = blockIdx.x * 256 + threadIdx.x;
    int n = t / 50;
    int c = t - n * 50;
    if (n >= Ntot) return;
    size_t off = (size_t)n * 200 + c * 4;
    float4 e = *(const float4*)(E + off);
    float4 a = *(const float4*)(g_agg + off);
    int d = c * 4;
    float4 o;
    o.x = tanhf(0.5f * (a.x + e.x) * (g[d + 0] * BNS) + bb[d + 0]);
    o.y = tanhf(0.5f * (a.y + e.y) * (g[d + 1] * BNS) + bb[d + 1]);
    o.z = tanhf(0.5f * (a.z + e.z) * (g[d + 2] * BNS) + bb[d + 2]);
    o.w = tanhf(0.5f * (a.w + e.w) * (g[d + 3] * BNS) + bb[d + 3]);
    *(float4*)(g_outE + off) = o;
}

// ---------------- fused stack + bn0 + conv7x3 + bn1 + relu -> Y ----------
struct IdxPtrs { const int* p[6]; };

__global__ void __launch_bounds__(256) buildY_k(
    const float* __restrict__ ms, const int* __restrict__ r_idx, IdxPtrs ip,
    const float* __restrict__ conv_w, const float* __restrict__ conv_b,
    const float* __restrict__ bn0_g, const float* __restrict__ bn0_b,
    const float* __restrict__ bn1_g, const float* __restrict__ bn1_b,
    int ent)
{
    __shared__ float xs[7][204];
    __shared__ float cw[4200];

    int b = blockIdx.x;
    int t = threadIdx.x;

    for (int i = t; i < 4200; i += 256) cw[i] = conv_w[i];
    if (t < 28) xs[t >> 2][200 + (t & 3)] = 0.f;

    float g0 = bn0_g[0] * BNS;
    float b0 = bn0_b[0];
    int ri = r_idx[b];

    for (int idx = t; idx < 1400; idx += 256) {
        int i = idx / 200;
        int d = idx - i * 200;
        float v;
        if (i == 0) {
            v = g_outR[(size_t)ri * 200 + d];
        } else {
            int k = i - 1;
            int eidx = ip.p[k][b];
            v = g_outE[(size_t)eidx * 200 + d] *
                g_outE[(size_t)(ent + k) * 200 + d] * ms[b * 6 + k];
        }
        xs[i][d] = v * g0 + b0;
    }
    __syncthreads();

    float* ybase = g_Y + (size_t)b * FEATK;
    // 200 filters x 25 groups of 8 output positions = 5000 items
    for (int it = t; it < 5000; it += 256) {
        int nf = it / 25;
        int pg = it - nf * 25;
        int p0 = pg * 8;
        float w[21];
#pragma unroll
        for (int q = 0; q < 21; q++) w[q] = cw[nf * 21 + q];
        float acc[8];
#pragma unroll
        for (int q = 0; q < 8; q++) acc[q] = 0.f;
#pragma unroll
        for (int i = 0; i < 7; i++) {
            float x[10];
#pragma unroll
            for (int q = 0; q < 10; q++) x[q] = xs[i][p0 + q];
#pragma unroll
            for (int q = 0; q < 8; q++)
                acc[q] += x[q] * w[i * 3 + 0] + x[q + 1] * w[i * 3 + 1] +
                          x[q + 2] * w[i * 3 + 2];
        }
        float cb = conv_b[nf];
        float g1 = bn1_g[nf] * BNS;
        float b1 = bn1_b[nf];
        float* yr = ybase + nf * 198;
#pragma unroll
        for (int q = 0; q < 8; q++) {
            int p = p0 + q;
            if (p < 198) yr[p] = fmaxf((acc[q] + cb) * g1 + b1, 0.f);
        }
    }
}

// ---------------- final: relu(bn2(fc + bias)) row-sum -> out[b] ----------
__global__ void final_k(const float* __restrict__ fc_b,
                        const float* __restrict__ g,
                        const float* __restrict__ bb,
                        float* __restrict__ out, int B)
{
    int gt = blockIdx.x * 256 + threadIdx.x;
    int wb = gt >> 5;
    int lane = gt & 31;
    if (wb >= B) return;
    float s = 0.f;
    for (int d = lane; d < 200; d += 32) {
        float v = (g_FCACC[(size_t)wb * 200 + d] + fc_b[d]) * (g[d] * BNS) + bb[d];
        s += fmaxf(v, 0.f);
    }
#pragma unroll
    for (int o = 16; o; o >>= 1) s += __shfl_down_sync(0xffffffffu, s, o);
    if (lane == 0) out[wb] = s;
}

// ---------------- host orchestration ------------------------------------
extern "C" void kernel_launch(void* const* d_in, const int* in_sizes, int n_in,
                              void* d_out, int out_size)
{
    const float* E          = (const float*)d_in[0];
    const float* R          = (const float*)d_in[1];
    const float* w_alle     = (const float*)d_in[2];
    const float* w_addpos   = (const float*)d_in[3];
    const float* w_alleandr = (const float*)d_in[4];
    const float* w_rel      = (const float*)d_in[5];
    const float* conv_w     = (const float*)d_in[6];
    const float* conv_b     = (const float*)d_in[7];
    /* fc_w */
    const float* fc_w       = (const float*)d_in[8];
    const float* fc_b       = (const float*)d_in[9];
    const float* bnmp_g     = (const float*)d_in[10];
    const float* bnmp_b     = (const float*)d_in[11];
    const float* bn0_g      = (const float*)d_in[12];
    const float* bn0_b      = (const float*)d_in[13];
    const float* bn1_g      = (const float*)d_in[14];
    const float* bn1_b      = (const float*)d_in[15];
    const float* bn2_g      = (const float*)d_in[16];
    const float* bn2_b      = (const float*)d_in[17];
    const float* ms         = (const float*)d_in[18];
    const int*   hyperedge  = (const int*)d_in[19];
    const int*   edge_index = (const int*)d_in[20];
    const int*   edge_type  = (const int*)d_in[21];
    const int*   r_idx      = (const int*)d_in[22];
    IdxPtrs ip;
    for (int k = 0; k < 6; k++) ip.p[k] = (const int*)d_in[23 + k];

    const int Ntot  = in_sizes[0] / DD;   // 50006
    const int ent   = Ntot - 6;           // ent_num
    const int NR    = in_sizes[1] / DD;   // 2000
    const int H     = in_sizes[19] / 7;   // 100000
    const int NEdge = in_sizes[21];       // 600000
    const int Bsz   = in_sizes[22];       // 2048

    float *pT, *pU, *pComb, *pRW, *pOutR, *pEP, *pAgg, *pY, *pFC;
    cudaGetSymbolAddress((void**)&pT,    g_T);
    cudaGetSymbolAddress((void**)&pU,    g_U);
    cudaGetSymbolAddress((void**)&pComb, g_comb);
    cudaGetSymbolAddress((void**)&pRW,   g_RW);
    cudaGetSymbolAddress((void**)&pOutR, g_outR);
    cudaGetSymbolAddress((void**)&pEP,   g_EP);
    cudaGetSymbolAddress((void**)&pAgg,  g_agg);
    cudaGetSymbolAddress((void**)&pY,    g_Y);
    cudaGetSymbolAddress((void**)&pFC,   g_FCACC);

    cudaMemsetAsync(pAgg, 0, (size_t)Ntot * 200 * sizeof(float), 0);
    cudaMemsetAsync(pFC,  0, (size_t)Bsz * 200 * sizeof(float), 0);

    // T = w_alleandr @ w_addpos_top   (200x200)
    sgemm_k<false><<<dim3(2, 2, 1), 256>>>(w_alleandr, w_addpos, pT,
                                           200, 200, 200, 200, 200, 200, 1.f, 200);
    // U = w_alle @ T                  (1200x200)
    sgemm_k<false><<<dim3(2, 10, 1), 256>>>(w_alle, pT, pU,
                                            1200, 200, 200, 200, 200, 200, 1.f, 200);
    // comb (200 x 1400): fused P0..P5 | w_addpos_bot
    build_comb_k<<<(200 * 1400 + 255) / 256, 256>>>(E, w_addpos, ent);
    // RW = 0.5 * R @ T
    sgemm_k<false><<<dim3(2, (NR + 127) / 128, 1), 256>>>(R, pT, pRW,
                                            NR, 200, 200, 200, 200, 200, 0.5f, 200);
    // outR = R @ w_rel
    sgemm_k<false><<<dim3(2, (NR + 127) / 128, 1), 256>>>(R, w_rel, pOutR,
                                            NR, 200, 200, 200, 200, 200, 1.f, 200);
    // EP = E @ comb   (50006 x 1400, pitch 1408) -- the big precompute GEMM
    sgemm_k<false><<<dim3(11, (Ntot + 127) / 128, 1), 256>>>(E, pComb, pEP,
                                            Ntot, 1400, 200, 200, CPITCH, CPITCH,
                                            1.f, 200);
    // hembW: pure gather-sum per hyperedge (replaces e_all/hemb/msg GEMMs)
    hembw_k<<<(H * 50 + 255) / 256, 256>>>(hyperedge, H);
    // per-edge scatter into agg (segment_sum)
    edge_k<<<(NEdge * 50 + 255) / 256, 256>>>(edge_index, edge_type, NEdge);
    // outE = tanh(bn(0.5*agg + 0.5*E))
    oute_k<<<(Ntot * 50 + 255) / 256, 256>>>(E, bnmp_g, bnmp_b, Ntot);
    // Y = relu(bn1(conv(bn0(stack)))) flattened per batch row
    buildY_k<<<Bsz, 256>>>(ms, r_idx, ip, conv_w, conv_b,
                           bn0_g, bn0_b, bn1_g, bn1_b, ent);
    // FCACC += Y @ fc_w   (split-K, atomic accumulate)
    sgemm_k<true><<<dim3(2, (Bsz + 127) / 128, 25), 256>>>(pY, fc_w, pFC,
                                            Bsz, 200, FEATK, FEATK, 200, 200,
                                            1.f, 1584);
    // out[b] = sum_d relu(bn2(FCACC + fc_b))
    final_k<<<(Bsz * 32 + 255) / 256, 256>>>(fc_b, bn2_g, bn2_b,
                                             (float*)d_out, Bsz);
}

// round 5
// speedup vs baseline: 1.8360x; 1.8360x over previous
#include <cuda_runtime.h>
#include <math.h>

// BN scale: 1/sqrt(1 + 1e-5)
#define BNS 0.9999950000374997f

#define DD      200
#define NTOT_MX 50006
#define H_MX    100000
#define NE_MX   600000
#define B_MX    2048
#define NR_MX   2048
#define CPITCH  1408      // EP row pitch
#define FEATK   39600     // 200 * 198

// ---------------- static device scratch ----------------------------------
__device__ __align__(128) float g_T[200 * 200];
__device__ __align__(128) float g_U[1200 * 200];
__device__ __align__(128) float g_comb[200 * CPITCH];
__device__ __align__(128) float g_RW[(size_t)NR_MX * 200];
__device__ __align__(128) float g_outR[(size_t)NR_MX * 200];
__device__ __align__(128) float g_EP[(size_t)NTOT_MX * CPITCH];
__device__ __align__(128) float g_hembW[(size_t)H_MX * 200];
__device__ __align__(128) float g_agg[(size_t)NTOT_MX * 200];
__device__ __align__(128) float g_outE[(size_t)NTOT_MX * 200];
__device__ __align__(128) float g_Y[(size_t)B_MX * FEATK];
__device__ __align__(128) float g_FCACC[(size_t)B_MX * 200];

// =========================================================================
// tf32 tensor-core GEMM: C = alpha * A(MxK,row) @ B(KxN,row)
// Block tile 128x128, BK=8, 256 threads (8 warps, 2x4), warp tile 64x32,
// mma.sync.m16n8k8 tf32. Double-buffered smem in fragment order.
// Split-K via blockIdx.z (kChunk mult of 8; K mult of 8; N mult of 8).
// =========================================================================
__device__ __forceinline__ unsigned f2tf(float x) {
    unsigned y;
    asm("cvt.rna.tf32.f32 %0, %1;" : "=r"(y) : "f"(x));
    return y;
}
__device__ __forceinline__ void mma_tf32(float* c, const unsigned* a,
                                         const unsigned* b) {
    asm volatile(
        "mma.sync.aligned.m16n8k8.row.col.f32.tf32.tf32.f32 "
        "{%0,%1,%2,%3}, {%4,%5,%6,%7}, {%8,%9}, {%0,%1,%2,%3};"
        : "+f"(c[0]), "+f"(c[1]), "+f"(c[2]), "+f"(c[3])
        : "r"(a[0]), "r"(a[1]), "r"(a[2]), "r"(a[3]), "r"(b[0]), "r"(b[1]));
}
__device__ __forceinline__ void red2(float* p, float x, float y) {
    asm volatile("red.global.add.v2.f32 [%0], {%1, %2};"
                 :: "l"(p), "f"(x), "f"(y) : "memory");
}

template <bool ATOMIC>
__global__ void __launch_bounds__(256) mma_gemm_k(
    const float* __restrict__ A, const float* __restrict__ B,
    float* __restrict__ C, int M, int N, int K,
    int lda, int ldb, int ldc, float alpha, int kChunk)
{
    // A: 8 mfrags x 32 groups(lane) x 4 words(reg), XOR-swizzled groups
    // B: 16 nfrags x (32 lanes x 2 regs), padded row stride 66
    __shared__ __align__(16) unsigned As[2][1024];
    __shared__ __align__(16) unsigned Bs[2][1056];

    const int tid  = threadIdx.x;
    const int lane = tid & 31;
    const int warp = tid >> 5;
    const int wm = warp >> 2;   // 0..1  (64-row warp tiles)
    const int wn = warp & 3;    // 0..3  (32-col warp tiles)
    const int m0 = blockIdx.y * 128;
    const int n0 = blockIdx.x * 128;

    const int kBegin = blockIdx.z * kChunk;
    const int kEnd   = min(kBegin + kChunk, K);
    const int iters  = (kEnd - kBegin) >> 3;
    if (iters <= 0) return;

    // ---- A loader indices: thread -> (row m = tid>>1, k-half = tid&1)
    const int am    = tid >> 1;
    const int ac0q  = tid & 1;                     // c0 = ac0q*4
    const bool aVal = (m0 + am) < M;
    const float* Ap = A + (size_t)(m0 + am) * lda + (ac0q << 2) + kBegin;
    const int aG0   = ((am >> 4) << 5) + (am & 7) * 4;   // group base
    const int aReg  = ((am >> 3) & 1) + (ac0q << 1);

    // ---- B loader indices: thread -> (k = tid>>5, n0q = (tid&31)*4)
    const int bk    = tid >> 5;
    const int bn    = (tid & 31) << 2;
    const bool bVal = (n0 + bn) < N;
    const float* Bp = B + (size_t)(kBegin + bk) * ldb + n0 + bn;
    const int bBase = (bn >> 3) * 66 + (bk >> 2);
    const int bL0   = (bn & 7) * 4 + (bk & 3);

    float acc[4][4][4];
#pragma unroll
    for (int i = 0; i < 4; i++)
#pragma unroll
        for (int j = 0; j < 4; j++)
#pragma unroll
            for (int q = 0; q < 4; q++) acc[i][j][q] = 0.f;

    unsigned ar[4], br[4];

#define LOAD_TILE(IT)                                                        \
    {                                                                        \
        float4 av = make_float4(0.f, 0.f, 0.f, 0.f);                         \
        if (aVal) av = *(const float4*)(Ap + ((IT) << 3));                   \
        ar[0] = f2tf(av.x); ar[1] = f2tf(av.y);                              \
        ar[2] = f2tf(av.z); ar[3] = f2tf(av.w);                              \
        float4 bv = make_float4(0.f, 0.f, 0.f, 0.f);                         \
        if (bVal) bv = *(const float4*)(Bp + (size_t)((IT) << 3) * ldb);     \
        br[0] = f2tf(bv.x); br[1] = f2tf(bv.y);                              \
        br[2] = f2tf(bv.z); br[3] = f2tf(bv.w);                              \
    }
#define STORE_TILE(BUF)                                                      \
    {                                                                        \
        _Pragma("unroll")                                                    \
        for (int i = 0; i < 4; i++) {                                        \
            int g  = aG0 + i;                                                \
            int gs = g ^ ((g >> 3) & 7);                                     \
            As[BUF][(gs << 2) + aReg] = ar[i];                               \
        }                                                                    \
        _Pragma("unroll")                                                    \
        for (int i = 0; i < 4; i++)                                          \
            Bs[BUF][bBase + ((bL0 + (i << 2)) << 1)] = br[i];                \
    }

    LOAD_TILE(0);
    STORE_TILE(0);
    __syncthreads();

    for (int it = 0; it < iters; ++it) {
        const int cur = it & 1;
        if (it + 1 < iters) LOAD_TILE(it + 1);

        unsigned af[4][4], bf[4][2];
#pragma unroll
        for (int mf = 0; mf < 4; mf++) {
            int g  = (((wm << 2) + mf) << 5) + lane;
            int gs = g ^ ((g >> 3) & 7);
            uint4 t = *(const uint4*)&As[cur][gs << 2];
            af[mf][0] = t.x; af[mf][1] = t.y; af[mf][2] = t.z; af[mf][3] = t.w;
        }
#pragma unroll
        for (int nf = 0; nf < 4; nf++) {
            uint2 t = *(const uint2*)&Bs[cur][((wn << 2) + nf) * 66 + (lane << 1)];
            bf[nf][0] = t.x; bf[nf][1] = t.y;
        }
#pragma unroll
        for (int mf = 0; mf < 4; mf++)
#pragma unroll
            for (int nf = 0; nf < 4; nf++)
                mma_tf32(acc[mf][nf], af[mf], bf[nf]);

        if (it + 1 < iters) {
            STORE_TILE(cur ^ 1);
            __syncthreads();
        }
    }
#undef LOAD_TILE
#undef STORE_TILE

    // ---- epilogue
#pragma unroll
    for (int mf = 0; mf < 4; mf++) {
#pragma unroll
        for (int nf = 0; nf < 4; nf++) {
            int row = m0 + wm * 64 + mf * 16 + (lane >> 2);
            int col = n0 + wn * 32 + nf * 8 + ((lane & 3) << 1);
            if (col >= N) continue;
            float* p = C + (size_t)row * ldc + col;
            if (row < M) {
                if (ATOMIC) red2(p, alpha * acc[mf][nf][0], alpha * acc[mf][nf][1]);
                else *(float2*)p = make_float2(alpha * acc[mf][nf][0],
                                               alpha * acc[mf][nf][1]);
            }
            if (row + 8 < M) {
                float* q = p + (size_t)8 * ldc;
                if (ATOMIC) red2(q, alpha * acc[mf][nf][2], alpha * acc[mf][nf][3]);
                else *(float2*)q = make_float2(alpha * acc[mf][nf][2],
                                               alpha * acc[mf][nf][3]);
            }
        }
    }
}

// ---------------- SIMT SGEMM (exact fp32) for the small precompute chain -
template <bool ATOMIC>
__global__ void __launch_bounds__(256) sgemm_k(
    const float* __restrict__ A, const float* __restrict__ B,
    float* __restrict__ C, int M, int Ncols, int K,
    int lda, int ldb, int ldc, float alpha, int kChunk)
{
    __shared__ float As[8][128];
    __shared__ float Bs[8][128];

    const int tid = threadIdx.x;
    const int tx = tid & 15;
    const int ty = tid >> 4;
    const int m0 = blockIdx.y * 128;
    const int n0 = blockIdx.x * 128;

    int kBegin = blockIdx.z * kChunk;
    int kEnd = kBegin + kChunk;
    if (kEnd > K) kEnd = K;

    const int aRow = tid >> 1;
    const int aK4  = (tid & 1) << 2;
    const int bRow = tid >> 5;
    const int bCol = (tid & 31) << 2;

    float acc[8][8];
#pragma unroll
    for (int i = 0; i < 8; i++)
#pragma unroll
        for (int j = 0; j < 8; j++) acc[i][j] = 0.f;

    for (int k0 = kBegin; k0 < kEnd; k0 += 8) {
        float4 av = make_float4(0.f, 0.f, 0.f, 0.f);
        if (m0 + aRow < M)
            av = *(const float4*)(A + (size_t)(m0 + aRow) * lda + (k0 + aK4));
        As[aK4 + 0][aRow] = av.x;
        As[aK4 + 1][aRow] = av.y;
        As[aK4 + 2][aRow] = av.z;
        As[aK4 + 3][aRow] = av.w;

        float4 bv = make_float4(0.f, 0.f, 0.f, 0.f);
        if (n0 + bCol < Ncols)
            bv = *(const float4*)(B + (size_t)(k0 + bRow) * ldb + (n0 + bCol));
        *(float4*)&Bs[bRow][bCol] = bv;

        __syncthreads();
#pragma unroll
        for (int kk = 0; kk < 8; kk++) {
            float ar[8], br[8];
#pragma unroll
            for (int i = 0; i < 8; i++) ar[i] = As[kk][ty * 8 + i];
#pragma unroll
            for (int j = 0; j < 8; j++) br[j] = Bs[kk][tx * 8 + j];
#pragma unroll
            for (int i = 0; i < 8; i++)
#pragma unroll
                for (int j = 0; j < 8; j++)
                    acc[i][j] = fmaf(ar[i], br[j], acc[i][j]);
        }
        __syncthreads();
    }

#pragma unroll
    for (int i = 0; i < 8; i++) {
        int m = m0 + ty * 8 + i;
        if (m >= M) continue;
        if (ATOMIC) {
#pragma unroll
            for (int jj = 0; jj < 8; jj += 2) {
                int n = n0 + tx * 8 + jj;
                if (n < Ncols)
                    red2(C + (size_t)m * ldc + n,
                         alpha * acc[i][jj], alpha * acc[i][jj + 1]);
            }
        } else {
#pragma unroll
            for (int jj = 0; jj < 8; jj += 4) {
                int n = n0 + tx * 8 + jj;
                if (n < Ncols) {
                    float4 v = make_float4(alpha * acc[i][jj + 0],
                                           alpha * acc[i][jj + 1],
                                           alpha * acc[i][jj + 2],
                                           alpha * acc[i][jj + 3]);
                    *(float4*)(C + (size_t)m * ldc + n) = v;
                }
            }
        }
    }
}

// ---------------- build fused weight comb (200 x 1400) -------------------
__global__ void build_comb_k(const float* __restrict__ E,
                             const float* __restrict__ w_addpos, int ent)
{
    int idx = blockIdx.x * 256 + threadIdx.x;
    if (idx >= 200 * 1400) return;
    int i = idx / 1400;
    int c = idx - i * 1400;
    float v;
    if (c < 1200) {
        int k = c / 200;
        int j = c - k * 200;
        v = 0.5f * E[(size_t)(ent + k) * DD + i] *
            g_U[(size_t)(k * 200 + i) * 200 + j];
    } else {
        v = w_addpos[(size_t)(200 + i) * 200 + (c - 1200)];
    }
    g_comb[(size_t)i * CPITCH + c] = v;
}

// ---------------- hembW[h] = RW[he0] + sum_k EP[he_{k+1}, k*200 : +200] --
__global__ void hembw_k(const int* __restrict__ he, int H)
{
    int t = blockIdx.x * 256 + threadIdx.x;
    int h = t / 50;
    int c = t - h * 50;
    if (h >= H) return;
    const int* row = he + (size_t)h * 7;
    int r = row[0];
    float4 acc = *(const float4*)(g_RW + (size_t)r * 200 + c * 4);
#pragma unroll
    for (int k = 0; k < 6; k++) {
        int e = row[1 + k];
        float4 v = *(const float4*)(g_EP + (size_t)e * CPITCH + k * 200 + c * 4);
        acc.x += v.x; acc.y += v.y; acc.z += v.z; acc.w += v.w;
    }
    *(float4*)(g_hembW + (size_t)h * 200 + c * 4) = acc;
}

// ---------------- per-edge scatter: agg[seg] += hembW[et] + EW[gidx] -----
__global__ void edge_k(const int* __restrict__ ei,
                       const int* __restrict__ et, int NEdge)
{
    int t = blockIdx.x * 256 + threadIdx.x;
    int e = t / 50;
    int c = t - e * 50;
    if (e >= NEdge) return;
    int seg  = ei[e];
    int gidx = ei[NEdge + e];
    int h    = et[e];
    float4 a = *(const float4*)(g_hembW + (size_t)h * 200 + c * 4);
    float4 b = *(const float4*)(g_EP + (size_t)gidx * CPITCH + 1200 + c * 4);
    float* p = g_agg + (size_t)seg * 200 + c * 4;
    asm volatile("red.global.add.v4.f32 [%0], {%1, %2, %3, %4};"
                 :: "l"(p), "f"(a.x + b.x), "f"(a.y + b.y),
                    "f"(a.z + b.z), "f"(a.w + b.w) : "memory");
}

// ---------------- outE = tanh(bn(0.5*agg + 0.5*E)) -----------------------
__global__ void oute_k(const float* __restrict__ E,
                       const float* __restrict__ g,
                       const float* __restrict__ bb, int Ntot)
{
    int t = blockIdx.x * 256 + threadIdx.x;
    int n = t / 50;
    int c = t - n * 50;
    if (n >= Ntot) return;
    size_t off = (size_t)n * 200 + c * 4;
    float4 e = *(const float4*)(E + off);
    float4 a = *(const float4*)(g_agg + off);
    int d = c * 4;
    float4 o;
    o.x = tanhf(0.5f * (a.x + e.x) * (g[d + 0] * BNS) + bb[d + 0]);
    o.y = tanhf(0.5f * (a.y + e.y) * (g[d + 1] * BNS) + bb[d + 1]);
    o.z = tanhf(0.5f * (a.z + e.z) * (g[d + 2] * BNS) + bb[d + 2]);
    o.w = tanhf(0.5f * (a.w + e.w) * (g[d + 3] * BNS) + bb[d + 3]);
    *(float4*)(g_outE + off) = o;
}

// ---------------- fused stack + bn0 + conv7x3 + bn1 + relu -> Y ----------
struct IdxPtrs { const int* p[6]; };

__global__ void __launch_bounds__(256) buildY_k(
    const float* __restrict__ ms, const int* __restrict__ r_idx, IdxPtrs ip,
    const float* __restrict__ conv_w, const float* __restrict__ conv_b,
    const float* __restrict__ bn0_g, const float* __restrict__ bn0_b,
    const float* __restrict__ bn1_g, const float* __restrict__ bn1_b,
    int ent)
{
    __shared__ float xs[7][204];
    __shared__ float cw[4200];

    int b = blockIdx.x;
    int t = threadIdx.x;

    for (int i = t; i < 4200; i += 256) cw[i] = conv_w[i];
    if (t < 28) xs[t >> 2][200 + (t & 3)] = 0.f;

    float g0 = bn0_g[0] * BNS;
    float b0 = bn0_b[0];
    int ri = r_idx[b];

    for (int idx = t; idx < 1400; idx += 256) {
        int i = idx / 200;
        int d = idx - i * 200;
        float v;
        if (i == 0) {
            v = g_outR[(size_t)ri * 200 + d];
        } else {
            int k = i - 1;
            int eidx = ip.p[k][b];
            v = g_outE[(size_t)eidx * 200 + d] *
                g_outE[(size_t)(ent + k) * 200 + d] * ms[b * 6 + k];
        }
        xs[i][d] = v * g0 + b0;
    }
    __syncthreads();

    float* ybase = g_Y + (size_t)b * FEATK;
    for (int it = t; it < 5000; it += 256) {
        int nf = it / 25;
        int pg = it - nf * 25;
        int p0 = pg * 8;
        float w[21];
#pragma unroll
        for (int q = 0; q < 21; q++) w[q] = cw[nf * 21 + q];
        float acc[8];
#pragma unroll
        for (int q = 0; q < 8; q++) acc[q] = 0.f;
#pragma unroll
        for (int i = 0; i < 7; i++) {
            float x[10];
#pragma unroll
            for (int q = 0; q < 10; q++) x[q] = xs[i][p0 + q];
#pragma unroll
            for (int q = 0; q < 8; q++)
                acc[q] += x[q] * w[i * 3 + 0] + x[q + 1] * w[i * 3 + 1] +
                          x[q + 2] * w[i * 3 + 2];
        }
        float cb = conv_b[nf];
        float g1 = bn1_g[nf] * BNS;
        float b1 = bn1_b[nf];
        float* yr = ybase + nf * 198;
#pragma unroll
        for (int q = 0; q < 8; q++) {
            int p = p0 + q;
            if (p < 198) yr[p] = fmaxf((acc[q] + cb) * g1 + b1, 0.f);
        }
    }
}

// ---------------- final: relu(bn2(fc + bias)) row-sum -> out[b] ----------
__global__ void final_k(const float* __restrict__ fc_b,
                        const float* __restrict__ g,
                        const float* __restrict__ bb,
                        float* __restrict__ out, int B)
{
    int gt = blockIdx.x * 256 + threadIdx.x;
    int wb = gt >> 5;
    int lane = gt & 31;
    if (wb >= B) return;
    float s = 0.f;
    for (int d = lane; d < 200; d += 32) {
        float v = (g_FCACC[(size_t)wb * 200 + d] + fc_b[d]) * (g[d] * BNS) + bb[d];
        s += fmaxf(v, 0.f);
    }
#pragma unroll
    for (int o = 16; o; o >>= 1) s += __shfl_down_sync(0xffffffffu, s, o);
    if (lane == 0) out[wb] = s;
}

// ---------------- host orchestration ------------------------------------
extern "C" void kernel_launch(void* const* d_in, const int* in_sizes, int n_in,
                              void* d_out, int out_size)
{
    const float* E          = (const float*)d_in[0];
    const float* R          = (const float*)d_in[1];
    const float* w_alle     = (const float*)d_in[2];
    const float* w_addpos   = (const float*)d_in[3];
    const float* w_alleandr = (const float*)d_in[4];
    const float* w_rel      = (const float*)d_in[5];
    const float* conv_w     = (const float*)d_in[6];
    const float* conv_b     = (const float*)d_in[7];
    const float* fc_w       = (const float*)d_in[8];
    const float* fc_b       = (const float*)d_in[9];
    const float* bnmp_g     = (const float*)d_in[10];
    const float* bnmp_b     = (const float*)d_in[11];
    const float* bn0_g      = (const float*)d_in[12];
    const float* bn0_b      = (const float*)d_in[13];
    const float* bn1_g      = (const float*)d_in[14];
    const float* bn1_b      = (const float*)d_in[15];
    const float* bn2_g      = (const float*)d_in[16];
    const float* bn2_b      = (const float*)d_in[17];
    const float* ms         = (const float*)d_in[18];
    const int*   hyperedge  = (const int*)d_in[19];
    const int*   edge_index = (const int*)d_in[20];
    const int*   edge_type  = (const int*)d_in[21];
    const int*   r_idx      = (const int*)d_in[22];
    IdxPtrs ip;
    for (int k = 0; k < 6; k++) ip.p[k] = (const int*)d_in[23 + k];

    const int Ntot  = in_sizes[0] / DD;   // 50006
    const int ent   = Ntot - 6;
    const int NR    = in_sizes[1] / DD;   // 2000
    const int H     = in_sizes[19] / 7;   // 100000
    const int NEdge = in_sizes[21];       // 600000
    const int Bsz   = in_sizes[22];       // 2048

    float *pT, *pU, *pComb, *pRW, *pOutR, *pEP, *pAgg, *pY, *pFC;
    cudaGetSymbolAddress((void**)&pT,    g_T);
    cudaGetSymbolAddress((void**)&pU,    g_U);
    cudaGetSymbolAddress((void**)&pComb, g_comb);
    cudaGetSymbolAddress((void**)&pRW,   g_RW);
    cudaGetSymbolAddress((void**)&pOutR, g_outR);
    cudaGetSymbolAddress((void**)&pEP,   g_EP);
    cudaGetSymbolAddress((void**)&pAgg,  g_agg);
    cudaGetSymbolAddress((void**)&pY,    g_Y);
    cudaGetSymbolAddress((void**)&pFC,   g_FCACC);

    cudaMemsetAsync(pT,    0, 200 * 200 * sizeof(float), 0);
    cudaMemsetAsync(pU,    0, 1200 * 200 * sizeof(float), 0);
    cudaMemsetAsync(pRW,   0, (size_t)NR * 200 * sizeof(float), 0);
    cudaMemsetAsync(pOutR, 0, (size_t)NR * 200 * sizeof(float), 0);
    cudaMemsetAsync(pAgg,  0, (size_t)Ntot * 200 * sizeof(float), 0);
    cudaMemsetAsync(pFC,   0, (size_t)Bsz * 200 * sizeof(float), 0);

    // T = w_alleandr @ w_addpos_top  (exact fp32, split-K for occupancy)
    sgemm_k<true><<<dim3(2, 2, 13), 256>>>(w_alleandr, w_addpos, pT,
                                           200, 200, 200, 200, 200, 200, 1.f, 16);
    // U = w_alle @ T  (exact fp32)
    sgemm_k<true><<<dim3(2, 10, 5), 256>>>(w_alle, pT, pU,
                                           1200, 200, 200, 200, 200, 200, 1.f, 40);
    // comb (200 x 1400)
    build_comb_k<<<(200 * 1400 + 255) / 256, 256>>>(E, w_addpos, ent);
    // RW = 0.5 * R @ T  (exact fp32)
    sgemm_k<true><<<dim3(2, (NR + 127) / 128, 5), 256>>>(R, pT, pRW,
                                           NR, 200, 200, 200, 200, 200, 0.5f, 40);
    // outR = R @ w_rel  (tf32 tensor cores, split-K)
    mma_gemm_k<true><<<dim3(2, (NR + 127) / 128, 5), 256>>>(R, w_rel, pOutR,
                                           NR, 200, 200, 200, 200, 200, 1.f, 40);
    // EP = E @ comb  (tf32 tensor cores — the big precompute GEMM)
    mma_gemm_k<false><<<dim3(11, (Ntot + 127) / 128, 1), 256>>>(E, pComb, pEP,
                                           Ntot, 1400, 200, 200, CPITCH, CPITCH,
                                           1.f, 200);
    // hembW: gather-sum per hyperedge
    hembw_k<<<(H * 50 + 255) / 256, 256>>>(hyperedge, H);
    // per-edge scatter (vector RED)
    edge_k<<<(NEdge * 50 + 255) / 256, 256>>>(edge_index, edge_type, NEdge);
    // outE = tanh(bn(0.5*agg + 0.5*E))
    oute_k<<<(Ntot * 50 + 255) / 256, 256>>>(E, bnmp_g, bnmp_b, Ntot);
    // Y = relu(bn1(conv(bn0(stack))))
    buildY_k<<<Bsz, 256>>>(ms, r_idx, ip, conv_w, conv_b,
                           bn0_g, bn0_b, bn1_g, bn1_b, ent);
    // FCACC += Y @ fc_w  (tf32 tensor cores, split-K 25 x 1584)
    mma_gemm_k<true><<<dim3(2, (Bsz + 127) / 128, 25), 256>>>(pY, fc_w, pFC,
                                           Bsz, 200, FEATK, FEATK, 200, 200,
                                           1.f, 1584);
    // out[b] = sum_d relu(bn2(FCACC + fc_b))
    final_k<<<(Bsz * 32 + 255) / 256, 256>>>(fc_b, bn2_g, bn2_b,
                                             (float*)d_out, Bsz);
}

// round 6
// speedup vs baseline: 2.0100x; 1.0948x over previous
#include <cuda_runtime.h>
#include <cuda_fp16.h>
#include <math.h>

// BN scale: 1/sqrt(1 + 1e-5)
#define BNS 0.9999950000374997f

#define DD      200
#define NTOT_MX 50006
#define H_MX    100000
#define NE_MX   600000
#define B_MX    2048
#define NR_MX   2048
#define CPITCH  1408      // EP row pitch (halves)
#define FEATK   39600     // 200 * 198

// ---------------- static device scratch ----------------------------------
__device__ __align__(128) float  g_T[200 * 200];
__device__ __align__(128) float  g_U[1200 * 200];
__device__ __align__(128) float  g_comb[200 * CPITCH];
__device__ __align__(128) float  g_RW[(size_t)NR_MX * 200];
__device__ __align__(128) float  g_outR[(size_t)NR_MX * 200];
__device__ __align__(128) __half g_EP[(size_t)NTOT_MX * CPITCH];
__device__ __align__(128) __half g_hembW[(size_t)H_MX * 200];
__device__ __align__(128) float  g_agg[(size_t)NTOT_MX * 200];
__device__ __align__(128) float  g_outE[(size_t)NTOT_MX * 200];
__device__ __align__(128) __half g_Y[(size_t)B_MX * FEATK];
__device__ __align__(128) float  g_FCACC[(size_t)B_MX * 200];

// ---------------- helpers -------------------------------------------------
__device__ __forceinline__ unsigned f2tf(float x) {
    unsigned y;
    asm("cvt.rna.tf32.f32 %0, %1;" : "=r"(y) : "f"(x));
    return y;
}
__device__ __forceinline__ void mma_tf32(float* c, const unsigned* a,
                                         const unsigned* b) {
    asm volatile(
        "mma.sync.aligned.m16n8k8.row.col.f32.tf32.tf32.f32 "
        "{%0,%1,%2,%3}, {%4,%5,%6,%7}, {%8,%9}, {%0,%1,%2,%3};"
        : "+f"(c[0]), "+f"(c[1]), "+f"(c[2]), "+f"(c[3])
        : "r"(a[0]), "r"(a[1]), "r"(a[2]), "r"(a[3]), "r"(b[0]), "r"(b[1]));
}
__device__ __forceinline__ void red2(float* p, float x, float y) {
    asm volatile("red.global.add.v2.f32 [%0], {%1, %2};"
                 :: "l"(p), "f"(x), "f"(y) : "memory");
}
// vector-4 load returning float4, overloaded on element type
__device__ __forceinline__ float4 ld4(const float* p) {
    return *(const float4*)p;
}
__device__ __forceinline__ float4 ld4(const __half* p) {
    uint2 u = *(const uint2*)p;
    __half2 h0 = *(__half2*)&u.x;
    __half2 h1 = *(__half2*)&u.y;
    float2 a = __half22float2(h0);
    float2 b = __half22float2(h1);
    return make_float4(a.x, a.y, b.x, b.y);
}
// paired store, overloaded on destination type
__device__ __forceinline__ void store2(float* p, float x, float y) {
    *(float2*)p = make_float2(x, y);
}
__device__ __forceinline__ void store2(__half* p, float x, float y) {
    *(__half2*)p = __floats2half2_rn(x, y);
}

// =========================================================================
// tf32 tensor-core GEMM: C = alpha * A(MxK,row) @ B(KxN,row)
// AT in {float,__half} (loads converted to fp32->tf32), CT in {float,__half}.
// Block tile 128x128, BK=8, 256 threads, warp tile 64x32, double-buffered.
// Split-K via blockIdx.z (kChunk mult of 8; K mult of 8; N mult of 8).
// =========================================================================
template <class AT, class CT, bool ATOMIC>
__global__ void __launch_bounds__(256) mma_gemm_k(
    const AT* __restrict__ A, const float* __restrict__ B,
    CT* __restrict__ C, int M, int N, int K,
    int lda, int ldb, int ldc, float alpha, int kChunk)
{
    __shared__ __align__(16) unsigned As[2][1024];
    __shared__ __align__(16) unsigned Bs[2][1056];

    const int tid  = threadIdx.x;
    const int lane = tid & 31;
    const int warp = tid >> 5;
    const int wm = warp >> 2;
    const int wn = warp & 3;
    const int m0 = blockIdx.y * 128;
    const int n0 = blockIdx.x * 128;

    const int kBegin = blockIdx.z * kChunk;
    const int kEnd   = min(kBegin + kChunk, K);
    const int iters  = (kEnd - kBegin) >> 3;
    if (iters <= 0) return;

    const int am    = tid >> 1;
    const int ac0q  = tid & 1;
    const bool aVal = (m0 + am) < M;
    const AT* Ap = A + (size_t)(m0 + am) * lda + (ac0q << 2) + kBegin;
    const int aG0   = ((am >> 4) << 5) + (am & 7) * 4;
    const int aReg  = ((am >> 3) & 1) + (ac0q << 1);

    const int bk    = tid >> 5;
    const int bn    = (tid & 31) << 2;
    const bool bVal = (n0 + bn) < N;
    const float* Bp = B + (size_t)(kBegin + bk) * ldb + n0 + bn;
    const int bBase = (bn >> 3) * 66 + (bk >> 2);
    const int bL0   = (bn & 7) * 4 + (bk & 3);

    float acc[4][4][4];
#pragma unroll
    for (int i = 0; i < 4; i++)
#pragma unroll
        for (int j = 0; j < 4; j++)
#pragma unroll
            for (int q = 0; q < 4; q++) acc[i][j][q] = 0.f;

    unsigned ar[4], br[4];

#define LOAD_TILE(IT)                                                        \
    {                                                                        \
        float4 av = make_float4(0.f, 0.f, 0.f, 0.f);                         \
        if (aVal) av = ld4(Ap + ((IT) << 3));                                \
        ar[0] = f2tf(av.x); ar[1] = f2tf(av.y);                              \
        ar[2] = f2tf(av.z); ar[3] = f2tf(av.w);                              \
        float4 bv = make_float4(0.f, 0.f, 0.f, 0.f);                         \
        if (bVal) bv = *(const float4*)(Bp + (size_t)((IT) << 3) * ldb);     \
        br[0] = f2tf(bv.x); br[1] = f2tf(bv.y);                              \
        br[2] = f2tf(bv.z); br[3] = f2tf(bv.w);                              \
    }
#define STORE_TILE(BUF)                                                      \
    {                                                                        \
        _Pragma("unroll")                                                    \
        for (int i = 0; i < 4; i++) {                                        \
            int g  = aG0 + i;                                                \
            int gs = g ^ ((g >> 3) & 7);                                     \
            As[BUF][(gs << 2) + aReg] = ar[i];                               \
        }                                                                    \
        _Pragma("unroll")                                                    \
        for (int i = 0; i < 4; i++)                                          \
            Bs[BUF][bBase + ((bL0 + (i << 2)) << 1)] = br[i];                \
    }

    LOAD_TILE(0);
    STORE_TILE(0);
    __syncthreads();

    for (int it = 0; it < iters; ++it) {
        const int cur = it & 1;
        if (it + 1 < iters) LOAD_TILE(it + 1);

        unsigned af[4][4], bf[4][2];
#pragma unroll
        for (int mf = 0; mf < 4; mf++) {
            int g  = (((wm << 2) + mf) << 5) + lane;
            int gs = g ^ ((g >> 3) & 7);
            uint4 t = *(const uint4*)&As[cur][gs << 2];
            af[mf][0] = t.x; af[mf][1] = t.y; af[mf][2] = t.z; af[mf][3] = t.w;
        }
#pragma unroll
        for (int nf = 0; nf < 4; nf++) {
            uint2 t = *(const uint2*)&Bs[cur][((wn << 2) + nf) * 66 + (lane << 1)];
            bf[nf][0] = t.x; bf[nf][1] = t.y;
        }
#pragma unroll
        for (int mf = 0; mf < 4; mf++)
#pragma unroll
            for (int nf = 0; nf < 4; nf++)
                mma_tf32(acc[mf][nf], af[mf], bf[nf]);

        if (it + 1 < iters) {
            STORE_TILE(cur ^ 1);
            __syncthreads();
        }
    }
#undef LOAD_TILE
#undef STORE_TILE

#pragma unroll
    for (int mf = 0; mf < 4; mf++) {
#pragma unroll
        for (int nf = 0; nf < 4; nf++) {
            int row = m0 + wm * 64 + mf * 16 + (lane >> 2);
            int col = n0 + wn * 32 + nf * 8 + ((lane & 3) << 1);
            if (col >= N) continue;
            CT* p = C + (size_t)row * ldc + col;
            if (row < M) {
                if (ATOMIC) red2((float*)(void*)p,
                                 alpha * acc[mf][nf][0], alpha * acc[mf][nf][1]);
                else store2(p, alpha * acc[mf][nf][0], alpha * acc[mf][nf][1]);
            }
            if (row + 8 < M) {
                CT* q = p + (size_t)8 * ldc;
                if (ATOMIC) red2((float*)(void*)q,
                                 alpha * acc[mf][nf][2], alpha * acc[mf][nf][3]);
                else store2(q, alpha * acc[mf][nf][2], alpha * acc[mf][nf][3]);
            }
        }
    }
}

// ---------------- SIMT SGEMM (exact fp32) for the small precompute chain -
template <bool ATOMIC>
__global__ void __launch_bounds__(256) sgemm_k(
    const float* __restrict__ A, const float* __restrict__ B,
    float* __restrict__ C, int M, int Ncols, int K,
    int lda, int ldb, int ldc, float alpha, int kChunk)
{
    __shared__ float As[8][128];
    __shared__ float Bs[8][128];

    const int tid = threadIdx.x;
    const int tx = tid & 15;
    const int ty = tid >> 4;
    const int m0 = blockIdx.y * 128;
    const int n0 = blockIdx.x * 128;

    int kBegin = blockIdx.z * kChunk;
    int kEnd = kBegin + kChunk;
    if (kEnd > K) kEnd = K;

    const int aRow = tid >> 1;
    const int aK4  = (tid & 1) << 2;
    const int bRow = tid >> 5;
    const int bCol = (tid & 31) << 2;

    float acc[8][8];
#pragma unroll
    for (int i = 0; i < 8; i++)
#pragma unroll
        for (int j = 0; j < 8; j++) acc[i][j] = 0.f;

    for (int k0 = kBegin; k0 < kEnd; k0 += 8) {
        float4 av = make_float4(0.f, 0.f, 0.f, 0.f);
        if (m0 + aRow < M)
            av = *(const float4*)(A + (size_t)(m0 + aRow) * lda + (k0 + aK4));
        As[aK4 + 0][aRow] = av.x;
        As[aK4 + 1][aRow] = av.y;
        As[aK4 + 2][aRow] = av.z;
        As[aK4 + 3][aRow] = av.w;

        float4 bv = make_float4(0.f, 0.f, 0.f, 0.f);
        if (n0 + bCol < Ncols)
            bv = *(const float4*)(B + (size_t)(k0 + bRow) * ldb + (n0 + bCol));
        *(float4*)&Bs[bRow][bCol] = bv;

        __syncthreads();
#pragma unroll
        for (int kk = 0; kk < 8; kk++) {
            float ar[8], br[8];
#pragma unroll
            for (int i = 0; i < 8; i++) ar[i] = As[kk][ty * 8 + i];
#pragma unroll
            for (int j = 0; j < 8; j++) br[j] = Bs[kk][tx * 8 + j];
#pragma unroll
            for (int i = 0; i < 8; i++)
#pragma unroll
                for (int j = 0; j < 8; j++)
                    acc[i][j] = fmaf(ar[i], br[j], acc[i][j]);
        }
        __syncthreads();
    }

#pragma unroll
    for (int i = 0; i < 8; i++) {
        int m = m0 + ty * 8 + i;
        if (m >= M) continue;
        if (ATOMIC) {
#pragma unroll
            for (int jj = 0; jj < 8; jj += 2) {
                int n = n0 + tx * 8 + jj;
                if (n < Ncols)
                    red2(C + (size_t)m * ldc + n,
                         alpha * acc[i][jj], alpha * acc[i][jj + 1]);
            }
        } else {
#pragma unroll
            for (int jj = 0; jj < 8; jj += 4) {
                int n = n0 + tx * 8 + jj;
                if (n < Ncols) {
                    float4 v = make_float4(alpha * acc[i][jj + 0],
                                           alpha * acc[i][jj + 1],
                                           alpha * acc[i][jj + 2],
                                           alpha * acc[i][jj + 3]);
                    *(float4*)(C + (size_t)m * ldc + n) = v;
                }
            }
        }
    }
}

// ---------------- build fused weight comb (200 x 1400) -------------------
__global__ void build_comb_k(const float* __restrict__ E,
                             const float* __restrict__ w_addpos, int ent)
{
    int idx = blockIdx.x * 256 + threadIdx.x;
    if (idx >= 200 * 1400) return;
    int i = idx / 1400;
    int c = idx - i * 1400;
    float v;
    if (c < 1200) {
        int k = c / 200;
        int j = c - k * 200;
        v = 0.5f * E[(size_t)(ent + k) * DD + i] *
            g_U[(size_t)(k * 200 + i) * 200 + j];
    } else {
        v = w_addpos[(size_t)(200 + i) * 200 + (c - 1200)];
    }
    g_comb[(size_t)i * CPITCH + c] = v;
}

// ---------------- hembW[h] = RW[he0] + sum_k EP[he_{k+1}, k*200 : +200] --
__global__ void hembw_k(const int* __restrict__ he, int H)
{
    int t = blockIdx.x * 256 + threadIdx.x;
    int h = t / 50;
    int c = t - h * 50;
    if (h >= H) return;
    const int* row = he + (size_t)h * 7;
    int r = row[0];
    float4 acc = *(const float4*)(g_RW + (size_t)r * 200 + c * 4);
#pragma unroll
    for (int k = 0; k < 6; k++) {
        int e = row[1 + k];
        float4 v = ld4(g_EP + (size_t)e * CPITCH + k * 200 + c * 4);
        acc.x += v.x; acc.y += v.y; acc.z += v.z; acc.w += v.w;
    }
    __half* dst = g_hembW + (size_t)h * 200 + c * 4;
    ((__half2*)dst)[0] = __floats2half2_rn(acc.x, acc.y);
    ((__half2*)dst)[1] = __floats2half2_rn(acc.z, acc.w);
}

// ---------------- per-edge scatter: agg[seg] += hembW[et] + EP[gidx] -----
__global__ void edge_k(const int* __restrict__ ei,
                       const int* __restrict__ et, int NEdge)
{
    int t = blockIdx.x * 256 + threadIdx.x;
    int e = t / 50;
    int c = t - e * 50;
    if (e >= NEdge) return;
    int seg  = ei[e];
    int gidx = ei[NEdge + e];
    int h    = et[e];
    float4 a = ld4(g_hembW + (size_t)h * 200 + c * 4);
    float4 b = ld4(g_EP + (size_t)gidx * CPITCH + 1200 + c * 4);
    float* p = g_agg + (size_t)seg * 200 + c * 4;
    asm volatile("red.global.add.v4.f32 [%0], {%1, %2, %3, %4};"
                 :: "l"(p), "f"(a.x + b.x), "f"(a.y + b.y),
                    "f"(a.z + b.z), "f"(a.w + b.w) : "memory");
}

// ---------------- outE = tanh(bn(0.5*agg + 0.5*E)) -----------------------
__global__ void oute_k(const float* __restrict__ E,
                       const float* __restrict__ g,
                       const float* __restrict__ bb, int Ntot)
{
    int t = blockIdx.x * 256 + threadIdx.x;
    int n = t / 50;
    int c = t - n * 50;
    if (n >= Ntot) return;
    size_t off = (size_t)n * 200 + c * 4;
    float4 e = *(const float4*)(E + off);
    float4 a = *(const float4*)(g_agg + off);
    int d = c * 4;
    float4 o;
    o.x = tanhf(0.5f * (a.x + e.x) * (g[d + 0] * BNS) + bb[d + 0]);
    o.y = tanhf(0.5f * (a.y + e.y) * (g[d + 1] * BNS) + bb[d + 1]);
    o.z = tanhf(0.5f * (a.z + e.z) * (g[d + 2] * BNS) + bb[d + 2]);
    o.w = tanhf(0.5f * (a.w + e.w) * (g[d + 3] * BNS) + bb[d + 3]);
    *(float4*)(g_outE + off) = o;
}

// ---------------- fused stack + bn0 + conv7x3 + bn1 + relu -> Y (fp16) ---
struct IdxPtrs { const int* p[6]; };

__global__ void __launch_bounds__(256) buildY_k(
    const float* __restrict__ ms, const int* __restrict__ r_idx, IdxPtrs ip,
    const float* __restrict__ conv_w, const float* __restrict__ conv_b,
    const float* __restrict__ bn0_g, const float* __restrict__ bn0_b,
    const float* __restrict__ bn1_g, const float* __restrict__ bn1_b,
    int ent)
{
    __shared__ float xs[7][204];
    __shared__ float cw[4200];

    int b = blockIdx.x;
    int t = threadIdx.x;

    for (int i = t; i < 4200; i += 256) cw[i] = conv_w[i];
    if (t < 28) xs[t >> 2][200 + (t & 3)] = 0.f;

    float g0 = bn0_g[0] * BNS;
    float b0 = bn0_b[0];
    int ri = r_idx[b];

    for (int idx = t; idx < 1400; idx += 256) {
        int i = idx / 200;
        int d = idx - i * 200;
        float v;
        if (i == 0) {
            v = g_outR[(size_t)ri * 200 + d];
        } else {
            int k = i - 1;
            int eidx = ip.p[k][b];
            v = g_outE[(size_t)eidx * 200 + d] *
                g_outE[(size_t)(ent + k) * 200 + d] * ms[b * 6 + k];
        }
        xs[i][d] = v * g0 + b0;
    }
    __syncthreads();

    __half* ybase = g_Y + (size_t)b * FEATK;
    for (int it = t; it < 5000; it += 256) {
        int nf = it / 25;
        int pg = it - nf * 25;
        int p0 = pg * 8;
        float w[21];
#pragma unroll
        for (int q = 0; q < 21; q++) w[q] = cw[nf * 21 + q];
        float acc[8];
#pragma unroll
        for (int q = 0; q < 8; q++) acc[q] = 0.f;
#pragma unroll
        for (int i = 0; i < 7; i++) {
            float x[10];
#pragma unroll
            for (int q = 0; q < 10; q++) x[q] = xs[i][p0 + q];
#pragma unroll
            for (int q = 0; q < 8; q++)
                acc[q] += x[q] * w[i * 3 + 0] + x[q + 1] * w[i * 3 + 1] +
                          x[q + 2] * w[i * 3 + 2];
        }
        float cb = conv_b[nf];
        float g1 = bn1_g[nf] * BNS;
        float b1 = bn1_b[nf];
        __half* yr = ybase + nf * 198 + p0;
        int lim = min(198 - p0, 8);   // 8 or 6, always even
#pragma unroll
        for (int q = 0; q < 8; q += 2) {
            if (q < lim) {
                float v0 = fmaxf((acc[q + 0] + cb) * g1 + b1, 0.f);
                float v1 = fmaxf((acc[q + 1] + cb) * g1 + b1, 0.f);
                *(__half2*)(yr + q) = __floats2half2_rn(v0, v1);
            }
        }
    }
}

// ---------------- final: relu(bn2(fc + bias)) row-sum -> out[b] ----------
__global__ void final_k(const float* __restrict__ fc_b,
                        const float* __restrict__ g,
                        const float* __restrict__ bb,
                        float* __restrict__ out, int B)
{
    int gt = blockIdx.x * 256 + threadIdx.x;
    int wb = gt >> 5;
    int lane = gt & 31;
    if (wb >= B) return;
    float s = 0.f;
    for (int d = lane; d < 200; d += 32) {
        float v = (g_FCACC[(size_t)wb * 200 + d] + fc_b[d]) * (g[d] * BNS) + bb[d];
        s += fmaxf(v, 0.f);
    }
#pragma unroll
    for (int o = 16; o; o >>= 1) s += __shfl_down_sync(0xffffffffu, s, o);
    if (lane == 0) out[wb] = s;
}

// ---------------- host orchestration ------------------------------------
extern "C" void kernel_launch(void* const* d_in, const int* in_sizes, int n_in,
                              void* d_out, int out_size)
{
    const float* E          = (const float*)d_in[0];
    const float* R          = (const float*)d_in[1];
    const float* w_alle     = (const float*)d_in[2];
    const float* w_addpos   = (const float*)d_in[3];
    const float* w_alleandr = (const float*)d_in[4];
    const float* w_rel      = (const float*)d_in[5];
    const float* conv_w     = (const float*)d_in[6];
    const float* conv_b     = (const float*)d_in[7];
    const float* fc_w       = (const float*)d_in[8];
    const float* fc_b       = (const float*)d_in[9];
    const float* bnmp_g     = (const float*)d_in[10];
    const float* bnmp_b     = (const float*)d_in[11];
    const float* bn0_g      = (const float*)d_in[12];
    const float* bn0_b      = (const float*)d_in[13];
    const float* bn1_g      = (const float*)d_in[14];
    const float* bn1_b      = (const float*)d_in[15];
    const float* bn2_g      = (const float*)d_in[16];
    const float* bn2_b      = (const float*)d_in[17];
    const float* ms         = (const float*)d_in[18];
    const int*   hyperedge  = (const int*)d_in[19];
    const int*   edge_index = (const int*)d_in[20];
    const int*   edge_type  = (const int*)d_in[21];
    const int*   r_idx      = (const int*)d_in[22];
    IdxPtrs ip;
    for (int k = 0; k < 6; k++) ip.p[k] = (const int*)d_in[23 + k];

    const int Ntot  = in_sizes[0] / DD;   // 50006
    const int ent   = Ntot - 6;
    const int NR    = in_sizes[1] / DD;   // 2000
    const int H     = in_sizes[19] / 7;   // 100000
    const int NEdge = in_sizes[21];       // 600000
    const int Bsz   = in_sizes[22];       // 2048

    float *pT, *pU, *pComb, *pRW, *pOutR, *pAgg, *pFC;
    __half *pEP, *pY;
    cudaGetSymbolAddress((void**)&pT,    g_T);
    cudaGetSymbolAddress((void**)&pU,    g_U);
    cudaGetSymbolAddress((void**)&pComb, g_comb);
    cudaGetSymbolAddress((void**)&pRW,   g_RW);
    cudaGetSymbolAddress((void**)&pOutR, g_outR);
    cudaGetSymbolAddress((void**)&pEP,   g_EP);
    cudaGetSymbolAddress((void**)&pAgg,  g_agg);
    cudaGetSymbolAddress((void**)&pY,    g_Y);
    cudaGetSymbolAddress((void**)&pFC,   g_FCACC);

    cudaMemsetAsync(pT,    0, 200 * 200 * sizeof(float), 0);
    cudaMemsetAsync(pU,    0, 1200 * 200 * sizeof(float), 0);
    cudaMemsetAsync(pRW,   0, (size_t)NR * 200 * sizeof(float), 0);
    cudaMemsetAsync(pOutR, 0, (size_t)NR * 200 * sizeof(float), 0);
    cudaMemsetAsync(pAgg,  0, (size_t)Ntot * 200 * sizeof(float), 0);
    cudaMemsetAsync(pFC,   0, (size_t)Bsz * 200 * sizeof(float), 0);

    // T = w_alleandr @ w_addpos_top  (exact fp32, split-K)
    sgemm_k<true><<<dim3(2, 2, 13), 256>>>(w_alleandr, w_addpos, pT,
                                           200, 200, 200, 200, 200, 200, 1.f, 16);
    // U = w_alle @ T  (exact fp32)
    sgemm_k<true><<<dim3(2, 10, 5), 256>>>(w_alle, pT, pU,
                                           1200, 200, 200, 200, 200, 200, 1.f, 40);
    // comb (200 x 1400)
    build_comb_k<<<(200 * 1400 + 255) / 256, 256>>>(E, w_addpos, ent);
    // RW = 0.5 * R @ T  (exact fp32)
    sgemm_k<true><<<dim3(2, (NR + 127) / 128, 5), 256>>>(R, pT, pRW,
                                           NR, 200, 200, 200, 200, 200, 0.5f, 40);
    // outR = R @ w_rel  (tf32 MMA, split-K, fp32 out)
    mma_gemm_k<float, float, true><<<dim3(2, (NR + 127) / 128, 5), 256>>>(
        R, w_rel, pOutR, NR, 200, 200, 200, 200, 200, 1.f, 40);
    // EP = E @ comb  (tf32 MMA, fp16 out — halves write + downstream gathers)
    mma_gemm_k<float, __half, false><<<dim3(11, (Ntot + 127) / 128, 1), 256>>>(
        E, pComb, pEP, Ntot, 1400, 200, 200, CPITCH, CPITCH, 1.f, 200);
    // hembW: gather-sum per hyperedge (fp32 accum, fp16 store)
    hembw_k<<<(H * 50 + 255) / 256, 256>>>(hyperedge, H);
    // per-edge scatter (fp16 gathers, fp32 vector RED)
    edge_k<<<(NEdge * 50 + 255) / 256, 256>>>(edge_index, edge_type, NEdge);
    // outE = tanh(bn(0.5*agg + 0.5*E))
    oute_k<<<(Ntot * 50 + 255) / 256, 256>>>(E, bnmp_g, bnmp_b, Ntot);
    // Y = relu(bn1(conv(bn0(stack)))) -> fp16
    buildY_k<<<Bsz, 256>>>(ms, r_idx, ip, conv_w, conv_b,
                           bn0_g, bn0_b, bn1_g, bn1_b, ent);
    // FCACC += Y @ fc_w  (tf32 MMA, fp16 A, split-K 25)
    mma_gemm_k<__half, float, true><<<dim3(2, (Bsz + 127) / 128, 25), 256>>>(
        pY, fc_w, pFC, Bsz, 200, FEATK, FEATK, 200, 200, 1.f, 1584);
    // out[b] = sum_d relu(bn2(FCACC + fc_b))
    final_k<<<(Bsz * 32 + 255) / 256, 256>>>(fc_b, bn2_g, bn2_b,
                                             (float*)d_out, Bsz);
}

// round 7
// speedup vs baseline: 2.6682x; 1.3275x over previous
#include <cuda_runtime.h>
#include <cuda_fp16.h>
#include <math.h>

// BN scale: 1/sqrt(1 + 1e-5)
#define BNS 0.9999950000374997f

#define DD      200
#define NTOT_MX 50006
#define H_MX    100000
#define NE_MX   600000
#define B_MX    2048
#define NR_MX   2048
#define CPITCH  1408      // EP row pitch (halves)
#define FEATK   39600     // 200 * 198

// ---------------- static device scratch ----------------------------------
__device__ __align__(128) float  g_T[200 * 200];
__device__ __align__(128) float  g_U[1200 * 200];
__device__ __align__(128) float  g_comb[200 * CPITCH];
__device__ __align__(128) float  g_RW[(size_t)NR_MX * 200];
__device__ __align__(128) float  g_outR[(size_t)NR_MX * 200];
__device__ __align__(128) __half g_EP[(size_t)NTOT_MX * CPITCH];
__device__ __align__(128) __half g_hembW[(size_t)H_MX * 200];
__device__ __align__(128) float  g_agg[(size_t)NTOT_MX * 200];
__device__ __align__(128) float  g_outE[(size_t)NTOT_MX * 200];
__device__ __align__(128) __half g_Y[(size_t)B_MX * FEATK];
__device__ __align__(128) float  g_FCACC[(size_t)B_MX * 200];

// ---------------- helpers -------------------------------------------------
__device__ __forceinline__ unsigned pack2(float a, float b) {
    __half2 h = __floats2half2_rn(a, b);
    return *(unsigned*)&h;
}
__device__ __forceinline__ void red2(float* p, float x, float y) {
    asm volatile("red.global.add.v2.f32 [%0], {%1, %2};"
                 :: "l"(p), "f"(x), "f"(y) : "memory");
}
__device__ __forceinline__ float4 ld4(const float* p) {
    return *(const float4*)p;
}
__device__ __forceinline__ float4 ld4(const __half* p) {
    uint2 u = *(const uint2*)p;
    __half2 h0 = *(__half2*)&u.x;
    __half2 h1 = *(__half2*)&u.y;
    float2 a = __half22float2(h0);
    float2 b = __half22float2(h1);
    return make_float4(a.x, a.y, b.x, b.y);
}
__device__ __forceinline__ void store2(float* p, float x, float y) {
    *(float2*)p = make_float2(x, y);
}
__device__ __forceinline__ void store2(__half* p, float x, float y) {
    *(__half2*)p = __floats2half2_rn(x, y);
}
// 8 consecutive A elements -> 4 packed half2 words
__device__ __forceinline__ uint4 ldA8(const float* p) {
    float4 x = *(const float4*)p;
    float4 y = *(const float4*)(p + 4);
    uint4 r;
    r.x = pack2(x.x, x.y); r.y = pack2(x.z, x.w);
    r.z = pack2(y.x, y.y); r.w = pack2(y.z, y.w);
    return r;
}
__device__ __forceinline__ uint4 ldA8(const __half* p) {
    return *(const uint4*)p;
}
// 2 consecutive A elements -> packed half2 (for k8 tail)
__device__ __forceinline__ unsigned ldA2(const float* p) {
    float2 v = *(const float2*)p;
    return pack2(v.x, v.y);
}
__device__ __forceinline__ unsigned ldA2(const __half* p) {
    return *(const unsigned*)p;
}

__device__ __forceinline__ void mma_f16_k16(float* c, const unsigned* a,
                                            const unsigned* b) {
    asm volatile(
        "mma.sync.aligned.m16n8k16.row.col.f32.f16.f16.f32 "
        "{%0,%1,%2,%3}, {%4,%5,%6,%7}, {%8,%9}, {%0,%1,%2,%3};"
        : "+f"(c[0]), "+f"(c[1]), "+f"(c[2]), "+f"(c[3])
        : "r"(a[0]), "r"(a[1]), "r"(a[2]), "r"(a[3]), "r"(b[0]), "r"(b[1]));
}
__device__ __forceinline__ void mma_f16_k8(float* c, const unsigned* a,
                                           unsigned b) {
    asm volatile(
        "mma.sync.aligned.m16n8k8.row.col.f32.f16.f16.f32 "
        "{%0,%1,%2,%3}, {%4,%5}, {%6}, {%0,%1,%2,%3};"
        : "+f"(c[0]), "+f"(c[1]), "+f"(c[2]), "+f"(c[3])
        : "r"(a[0]), "r"(a[1]), "r"(b));
}

// =========================================================================
// fp16 tensor-core GEMM (fp32 accum): C = alpha * A(MxK,row) @ B(KxN,row)
// Block 128x128, BK=16, 256 threads (8 warps 2x4), warp tile 64x32,
// mma.sync.m16n8k16. Double-buffered fragment-order smem.
// kChunk: multiple of 8 (a k8 tail handles kChunk%16==8). N multiple of 8.
// =========================================================================
template <class AT, class CT, bool ATOMIC>
__global__ void __launch_bounds__(256) hmma_gemm_k(
    const AT* __restrict__ A, const float* __restrict__ B,
    CT* __restrict__ C, int M, int N, int K,
    int lda, int ldb, int ldc, float alpha, int kChunk)
{
    // A: 8 mfrags x 32 chunks x 4 words (chunk-swizzled) = 1024 u32
    // B: 16 nfrags x (32 lanes x 2 regs), padded stride 66 = 1056 u32
    __shared__ __align__(16) unsigned As[2][1024];
    __shared__ __align__(16) unsigned Bs[2][1056];

    const int tid  = threadIdx.x;
    const int lane = tid & 31;
    const int warp = tid >> 5;
    const int wm = warp >> 2;
    const int wn = warp & 3;
    const int m0 = blockIdx.y * 128;
    const int n0b = blockIdx.x * 128;

    const int kBegin = blockIdx.z * kChunk;
    const int kEnd   = min(kBegin + kChunk, K);
    const int iters  = (kEnd - kBegin) >> 4;
    const bool tail8 = ((kEnd - kBegin) & 8) != 0;

    // ---- A loader: thread -> (row am, k-half khalf)
    const int am    = tid >> 1;
    const int khalf = tid & 1;
    const bool aVal = (m0 + am) < M;
    const AT* Ap = A + (size_t)(m0 + am) * lda + kBegin + khalf * 8;
    const int amf  = am >> 4;
    const int ar   = am & 15;
    const int arl  = ar & 7;
    const int aReg = (khalf << 1) | (ar >> 3);

    // ---- B loader: thread -> (k-pair bkp, 2 cols bn0)
    const int bkp = (tid >> 6) & 3;
    const int bn0 = (tid & 63) << 1;
    const bool bVal = (n0b + bn0) < N;
    const float* Bp = B + (size_t)kBegin * ldb + n0b + bn0;
    const int bnf = bn0 >> 3;
    const int bLane0 = (bn0 & 7) * 4 + bkp;

    float acc[4][4][4];
#pragma unroll
    for (int i = 0; i < 4; i++)
#pragma unroll
        for (int j = 0; j < 4; j++)
#pragma unroll
            for (int q = 0; q < 4; q++) acc[i][j][q] = 0.f;

    uint4 aS;
    unsigned bS[4];

#define LOAD_TILE(IT)                                                        \
    {                                                                        \
        aS = make_uint4(0u, 0u, 0u, 0u);                                     \
        if (aVal) aS = ldA8(Ap + ((IT) << 4));                               \
        float2 r0a = make_float2(0.f, 0.f), r0b = r0a, r1a = r0a, r1b = r0a; \
        if (bVal) {                                                          \
            const float* q_ = Bp + (size_t)((IT) << 4) * ldb;                \
            r0a = *(const float2*)(q_ + (size_t)(2 * bkp) * ldb);            \
            r0b = *(const float2*)(q_ + (size_t)(2 * bkp + 1) * ldb);        \
            r1a = *(const float2*)(q_ + (size_t)(2 * bkp + 8) * ldb);        \
            r1b = *(const float2*)(q_ + (size_t)(2 * bkp + 9) * ldb);        \
        }                                                                    \
        bS[0] = pack2(r0a.x, r0b.x);  /* i=0 reg=0 */                        \
        bS[1] = pack2(r1a.x, r1b.x);  /* i=0 reg=1 */                        \
        bS[2] = pack2(r0a.y, r0b.y);  /* i=1 reg=0 */                        \
        bS[3] = pack2(r1a.y, r1b.y);  /* i=1 reg=1 */                        \
    }
#define STORE_TILE(BUF)                                                      \
    {                                                                        \
        unsigned aw[4] = {aS.x, aS.y, aS.z, aS.w};                           \
        _Pragma("unroll")                                                    \
        for (int jj = 0; jj < 4; jj++) {                                     \
            int c_   = arl * 4 + jj;                                         \
            int phys = c_ ^ ((c_ >> 3) & 3);                                 \
            As[BUF][amf * 128 + phys * 4 + aReg] = aw[jj];                   \
        }                                                                    \
        Bs[BUF][bnf * 66 + bLane0 * 2 + 0]       = bS[0];                    \
        Bs[BUF][bnf * 66 + bLane0 * 2 + 1]       = bS[1];                    \
        Bs[BUF][bnf * 66 + (bLane0 + 4) * 2 + 0] = bS[2];                    \
        Bs[BUF][bnf * 66 + (bLane0 + 4) * 2 + 1] = bS[3];                    \
    }

    const int lphys = lane ^ ((lane >> 3) & 3);

    if (iters > 0) {
        LOAD_TILE(0);
        STORE_TILE(0);
        __syncthreads();
    }

    for (int it = 0; it < iters; ++it) {
        const int cur = it & 1;
        if (it + 1 < iters) LOAD_TILE(it + 1);

        unsigned af[4][4], bf[4][2];
#pragma unroll
        for (int mf = 0; mf < 4; mf++) {
            uint4 t = *(const uint4*)&As[cur][(wm * 4 + mf) * 128 + lphys * 4];
            af[mf][0] = t.x; af[mf][1] = t.y; af[mf][2] = t.z; af[mf][3] = t.w;
        }
#pragma unroll
        for (int nf = 0; nf < 4; nf++) {
            uint2 t = *(const uint2*)&Bs[cur][(wn * 4 + nf) * 66 + lane * 2];
            bf[nf][0] = t.x; bf[nf][1] = t.y;
        }
#pragma unroll
        for (int mf = 0; mf < 4; mf++)
#pragma unroll
            for (int nf = 0; nf < 4; nf++)
                mma_f16_k16(acc[mf][nf], af[mf], bf[nf]);

        if (it + 1 < iters) {
            STORE_TILE(cur ^ 1);
            __syncthreads();
        }
    }
#undef LOAD_TILE
#undef STORE_TILE

    // ---- k8 tail (direct from global)
    if (tail8) {
        const int kT = kEnd - 8;
        const int kOff = kT + 2 * (lane & 3);
        unsigned bt[4];
#pragma unroll
        for (int nf = 0; nf < 4; nf++) {
            int col = n0b + wn * 32 + nf * 8 + (lane >> 2);
            float v0 = 0.f, v1 = 0.f;
            if (col < N) {
                v0 = B[(size_t)kOff * ldb + col];
                v1 = B[(size_t)(kOff + 1) * ldb + col];
            }
            bt[nf] = pack2(v0, v1);
        }
#pragma unroll
        for (int mf = 0; mf < 4; mf++) {
            int r0 = m0 + wm * 64 + mf * 16 + (lane >> 2);
            unsigned at[2];
            at[0] = (r0 < M)     ? ldA2(A + (size_t)r0 * lda + kOff)       : 0u;
            at[1] = (r0 + 8 < M) ? ldA2(A + (size_t)(r0 + 8) * lda + kOff) : 0u;
#pragma unroll
            for (int nf = 0; nf < 4; nf++)
                mma_f16_k8(acc[mf][nf], at, bt[nf]);
        }
    }

    // ---- epilogue
#pragma unroll
    for (int mf = 0; mf < 4; mf++) {
#pragma unroll
        for (int nf = 0; nf < 4; nf++) {
            int row = m0 + wm * 64 + mf * 16 + (lane >> 2);
            int col = n0b + wn * 32 + nf * 8 + ((lane & 3) << 1);
            if (col >= N) continue;
            CT* p = C + (size_t)row * ldc + col;
            if (row < M) {
                if (ATOMIC) red2((float*)(void*)p,
                                 alpha * acc[mf][nf][0], alpha * acc[mf][nf][1]);
                else store2(p, alpha * acc[mf][nf][0], alpha * acc[mf][nf][1]);
            }
            if (row + 8 < M) {
                CT* q = p + (size_t)8 * ldc;
                if (ATOMIC) red2((float*)(void*)q,
                                 alpha * acc[mf][nf][2], alpha * acc[mf][nf][3]);
                else store2(q, alpha * acc[mf][nf][2], alpha * acc[mf][nf][3]);
            }
        }
    }
}

// ---------------- SIMT SGEMM (exact fp32) for the weight precompute ------
template <bool ATOMIC>
__global__ void __launch_bounds__(256) sgemm_k(
    const float* __restrict__ A, const float* __restrict__ B,
    float* __restrict__ C, int M, int Ncols, int K,
    int lda, int ldb, int ldc, float alpha, int kChunk)
{
    __shared__ float As[8][128];
    __shared__ float Bs[8][128];

    const int tid = threadIdx.x;
    const int tx = tid & 15;
    const int ty = tid >> 4;
    const int m0 = blockIdx.y * 128;
    const int n0 = blockIdx.x * 128;

    int kBegin = blockIdx.z * kChunk;
    int kEnd = kBegin + kChunk;
    if (kEnd > K) kEnd = K;

    const int aRow = tid >> 1;
    const int aK4  = (tid & 1) << 2;
    const int bRow = tid >> 5;
    const int bCol = (tid & 31) << 2;

    float acc[8][8];
#pragma unroll
    for (int i = 0; i < 8; i++)
#pragma unroll
        for (int j = 0; j < 8; j++) acc[i][j] = 0.f;

    for (int k0 = kBegin; k0 < kEnd; k0 += 8) {
        float4 av = make_float4(0.f, 0.f, 0.f, 0.f);
        if (m0 + aRow < M)
            av = *(const float4*)(A + (size_t)(m0 + aRow) * lda + (k0 + aK4));
        As[aK4 + 0][aRow] = av.x;
        As[aK4 + 1][aRow] = av.y;
        As[aK4 + 2][aRow] = av.z;
        As[aK4 + 3][aRow] = av.w;

        float4 bv = make_float4(0.f, 0.f, 0.f, 0.f);
        if (n0 + bCol < Ncols)
            bv = *(const float4*)(B + (size_t)(k0 + bRow) * ldb + (n0 + bCol));
        *(float4*)&Bs[bRow][bCol] = bv;

        __syncthreads();
#pragma unroll
        for (int kk = 0; kk < 8; kk++) {
            float ar[8], br[8];
#pragma unroll
            for (int i = 0; i < 8; i++) ar[i] = As[kk][ty * 8 + i];
#pragma unroll
            for (int j = 0; j < 8; j++) br[j] = Bs[kk][tx * 8 + j];
#pragma unroll
            for (int i = 0; i < 8; i++)
#pragma unroll
                for (int j = 0; j < 8; j++)
                    acc[i][j] = fmaf(ar[i], br[j], acc[i][j]);
        }
        __syncthreads();
    }

#pragma unroll
    for (int i = 0; i < 8; i++) {
        int m = m0 + ty * 8 + i;
        if (m >= M) continue;
        if (ATOMIC) {
#pragma unroll
            for (int jj = 0; jj < 8; jj += 2) {
                int n = n0 + tx * 8 + jj;
                if (n < Ncols)
                    red2(C + (size_t)m * ldc + n,
                         alpha * acc[i][jj], alpha * acc[i][jj + 1]);
            }
        } else {
#pragma unroll
            for (int jj = 0; jj < 8; jj += 4) {
                int n = n0 + tx * 8 + jj;
                if (n < Ncols) {
                    float4 v = make_float4(alpha * acc[i][jj + 0],
                                           alpha * acc[i][jj + 1],
                                           alpha * acc[i][jj + 2],
                                           alpha * acc[i][jj + 3]);
                    *(float4*)(C + (size_t)m * ldc + n) = v;
                }
            }
        }
    }
}

// ---------------- build fused weight comb (200 x 1400) -------------------
__global__ void build_comb_k(const float* __restrict__ E,
                             const float* __restrict__ w_addpos, int ent)
{
    int idx = blockIdx.x * 256 + threadIdx.x;
    if (idx >= 200 * 1400) return;
    int i = idx / 1400;
    int c = idx - i * 1400;
    float v;
    if (c < 1200) {
        int k = c / 200;
        int j = c - k * 200;
        v = 0.5f * E[(size_t)(ent + k) * DD + i] *
            g_U[(size_t)(k * 200 + i) * 200 + j];
    } else {
        v = w_addpos[(size_t)(200 + i) * 200 + (c - 1200)];
    }
    g_comb[(size_t)i * CPITCH + c] = v;
}

// ---------------- hembW[h] = RW[he0] + sum_k EP[he_{k+1}, k*200 : +200] --
__global__ void hembw_k(const int* __restrict__ he, int H)
{
    int t = blockIdx.x * 256 + threadIdx.x;
    int h = t / 50;
    int c = t - h * 50;
    if (h >= H) return;
    const int* row = he + (size_t)h * 7;
    int r = row[0];
    float4 acc = *(const float4*)(g_RW + (size_t)r * 200 + c * 4);
#pragma unroll
    for (int k = 0; k < 6; k++) {
        int e = row[1 + k];
        float4 v = ld4(g_EP + (size_t)e * CPITCH + k * 200 + c * 4);
        acc.x += v.x; acc.y += v.y; acc.z += v.z; acc.w += v.w;
    }
    __half* dst = g_hembW + (size_t)h * 200 + c * 4;
    ((__half2*)dst)[0] = __floats2half2_rn(acc.x, acc.y);
    ((__half2*)dst)[1] = __floats2half2_rn(acc.z, acc.w);
}

// ---------------- per-edge scatter: agg[seg] += hembW[et] + EP[gidx] -----
__global__ void edge_k(const int* __restrict__ ei,
                       const int* __restrict__ et, int NEdge)
{
    int t = blockIdx.x * 256 + threadIdx.x;
    int e = t / 50;
    int c = t - e * 50;
    if (e >= NEdge) return;
    int seg  = ei[e];
    int gidx = ei[NEdge + e];
    int h    = et[e];
    float4 a = ld4(g_hembW + (size_t)h * 200 + c * 4);
    float4 b = ld4(g_EP + (size_t)gidx * CPITCH + 1200 + c * 4);
    float* p = g_agg + (size_t)seg * 200 + c * 4;
    asm volatile("red.global.add.v4.f32 [%0], {%1, %2, %3, %4};"
                 :: "l"(p), "f"(a.x + b.x), "f"(a.y + b.y),
                    "f"(a.z + b.z), "f"(a.w + b.w) : "memory");
}

// ---------------- outE = tanh(bn(0.5*agg + 0.5*E)) -----------------------
__global__ void oute_k(const float* __restrict__ E,
                       const float* __restrict__ g,
                       const float* __restrict__ bb, int Ntot)
{
    int t = blockIdx.x * 256 + threadIdx.x;
    int n = t / 50;
    int c = t - n * 50;
    if (n >= Ntot) return;
    size_t off = (size_t)n * 200 + c * 4;
    float4 e = *(const float4*)(E + off);
    float4 a = *(const float4*)(g_agg + off);
    int d = c * 4;
    float4 o;
    o.x = tanhf(0.5f * (a.x + e.x) * (g[d + 0] * BNS) + bb[d + 0]);
    o.y = tanhf(0.5f * (a.y + e.y) * (g[d + 1] * BNS) + bb[d + 1]);
    o.z = tanhf(0.5f * (a.z + e.z) * (g[d + 2] * BNS) + bb[d + 2]);
    o.w = tanhf(0.5f * (a.w + e.w) * (g[d + 3] * BNS) + bb[d + 3]);
    *(float4*)(g_outE + off) = o;
}

// ---------------- fused stack + bn0 + conv7x3 + bn1 + relu -> Y (fp16) ---
struct IdxPtrs { const int* p[6]; };

__global__ void __launch_bounds__(256) buildY_k(
    const float* __restrict__ ms, const int* __restrict__ r_idx, IdxPtrs ip,
    const float* __restrict__ conv_w, const float* __restrict__ conv_b,
    const float* __restrict__ bn0_g, const float* __restrict__ bn0_b,
    const float* __restrict__ bn1_g, const float* __restrict__ bn1_b,
    int ent)
{
    __shared__ float xs[7][204];
    __shared__ float cw[4200];

    int b = blockIdx.x;
    int t = threadIdx.x;

    for (int i = t; i < 4200; i += 256) cw[i] = conv_w[i];
    if (t < 28) xs[t >> 2][200 + (t & 3)] = 0.f;

    float g0 = bn0_g[0] * BNS;
    float b0 = bn0_b[0];
    int ri = r_idx[b];

    for (int idx = t; idx < 1400; idx += 256) {
        int i = idx / 200;
        int d = idx - i * 200;
        float v;
        if (i == 0) {
            v = g_outR[(size_t)ri * 200 + d];
        } else {
            int k = i - 1;
            int eidx = ip.p[k][b];
            v = g_outE[(size_t)eidx * 200 + d] *
                g_outE[(size_t)(ent + k) * 200 + d] * ms[b * 6 + k];
        }
        xs[i][d] = v * g0 + b0;
    }
    __syncthreads();

    __half* ybase = g_Y + (size_t)b * FEATK;
    for (int it = t; it < 5000; it += 256) {
        int nf = it / 25;
        int pg = it - nf * 25;
        int p0 = pg * 8;
        float w[21];
#pragma unroll
        for (int q = 0; q < 21; q++) w[q] = cw[nf * 21 + q];
        float acc[8];
#pragma unroll
        for (int q = 0; q < 8; q++) acc[q] = 0.f;
#pragma unroll
        for (int i = 0; i < 7; i++) {
            float x[10];
#pragma unroll
            for (int q = 0; q < 10; q++) x[q] = xs[i][p0 + q];
#pragma unroll
            for (int q = 0; q < 8; q++)
                acc[q] += x[q] * w[i * 3 + 0] + x[q + 1] * w[i * 3 + 1] +
                          x[q + 2] * w[i * 3 + 2];
        }
        float cb = conv_b[nf];
        float g1 = bn1_g[nf] * BNS;
        float b1 = bn1_b[nf];
        __half* yr = ybase + nf * 198 + p0;
        int lim = min(198 - p0, 8);   // 8 or 6, always even
#pragma unroll
        for (int q = 0; q < 8; q += 2) {
            if (q < lim) {
                float v0 = fmaxf((acc[q + 0] + cb) * g1 + b1, 0.f);
                float v1 = fmaxf((acc[q + 1] + cb) * g1 + b1, 0.f);
                *(__half2*)(yr + q) = __floats2half2_rn(v0, v1);
            }
        }
    }
}

// ---------------- final: relu(bn2(fc + bias)) row-sum -> out[b] ----------
__global__ void final_k(const float* __restrict__ fc_b,
                        const float* __restrict__ g,
                        const float* __restrict__ bb,
                        float* __restrict__ out, int B)
{
    int gt = blockIdx.x * 256 + threadIdx.x;
    int wb = gt >> 5;
    int lane = gt & 31;
    if (wb >= B) return;
    float s = 0.f;
    for (int d = lane; d < 200; d += 32) {
        float v = (g_FCACC[(size_t)wb * 200 + d] + fc_b[d]) * (g[d] * BNS) + bb[d];
        s += fmaxf(v, 0.f);
    }
#pragma unroll
    for (int o = 16; o; o >>= 1) s += __shfl_down_sync(0xffffffffu, s, o);
    if (lane == 0) out[wb] = s;
}

// ---------------- host orchestration ------------------------------------
extern "C" void kernel_launch(void* const* d_in, const int* in_sizes, int n_in,
                              void* d_out, int out_size)
{
    const float* E          = (const float*)d_in[0];
    const float* R          = (const float*)d_in[1];
    const float* w_alle     = (const float*)d_in[2];
    const float* w_addpos   = (const float*)d_in[3];
    const float* w_alleandr = (const float*)d_in[4];
    const float* w_rel      = (const float*)d_in[5];
    const float* conv_w     = (const float*)d_in[6];
    const float* conv_b     = (const float*)d_in[7];
    const float* fc_w       = (const float*)d_in[8];
    const float* fc_b       = (const float*)d_in[9];
    const float* bnmp_g     = (const float*)d_in[10];
    const float* bnmp_b     = (const float*)d_in[11];
    const float* bn0_g      = (const float*)d_in[12];
    const float* bn0_b      = (const float*)d_in[13];
    const float* bn1_g      = (const float*)d_in[14];
    const float* bn1_b      = (const float*)d_in[15];
    const float* bn2_g      = (const float*)d_in[16];
    const float* bn2_b      = (const float*)d_in[17];
    const float* ms         = (const float*)d_in[18];
    const int*   hyperedge  = (const int*)d_in[19];
    const int*   edge_index = (const int*)d_in[20];
    const int*   edge_type  = (const int*)d_in[21];
    const int*   r_idx      = (const int*)d_in[22];
    IdxPtrs ip;
    for (int k = 0; k < 6; k++) ip.p[k] = (const int*)d_in[23 + k];

    const int Ntot  = in_sizes[0] / DD;   // 50006
    const int ent   = Ntot - 6;
    const int NR    = in_sizes[1] / DD;   // 2000
    const int H     = in_sizes[19] / 7;   // 100000
    const int NEdge = in_sizes[21];       // 600000
    const int Bsz   = in_sizes[22];       // 2048

    float *pT, *pU, *pComb, *pRW, *pOutR, *pAgg, *pFC;
    __half *pEP, *pY;
    cudaGetSymbolAddress((void**)&pT,    g_T);
    cudaGetSymbolAddress((void**)&pU,    g_U);
    cudaGetSymbolAddress((void**)&pComb, g_comb);
    cudaGetSymbolAddress((void**)&pRW,   g_RW);
    cudaGetSymbolAddress((void**)&pOutR, g_outR);
    cudaGetSymbolAddress((void**)&pEP,   g_EP);
    cudaGetSymbolAddress((void**)&pAgg,  g_agg);
    cudaGetSymbolAddress((void**)&pY,    g_Y);
    cudaGetSymbolAddress((void**)&pFC,   g_FCACC);

    cudaMemsetAsync(pT,   0, 200 * 200 * sizeof(float), 0);
    cudaMemsetAsync(pU,   0, 1200 * 200 * sizeof(float), 0);
    cudaMemsetAsync(pAgg, 0, (size_t)Ntot * 200 * sizeof(float), 0);
    cudaMemsetAsync(pFC,  0, (size_t)Bsz * 200 * sizeof(float), 0);

    // T = w_alleandr @ w_addpos_top  (exact fp32, split-K)
    sgemm_k<true><<<dim3(2, 2, 13), 256>>>(w_alleandr, w_addpos, pT,
                                           200, 200, 200, 200, 200, 200, 1.f, 16);
    // U = w_alle @ T  (exact fp32)
    sgemm_k<true><<<dim3(2, 10, 5), 256>>>(w_alle, pT, pU,
                                           1200, 200, 200, 200, 200, 200, 1.f, 40);
    // comb (200 x 1400)
    build_comb_k<<<(200 * 1400 + 255) / 256, 256>>>(E, w_addpos, ent);
    // RW = 0.5 * R @ T  (fp16 MMA, k8 tail)
    hmma_gemm_k<float, float, false><<<dim3(2, (NR + 127) / 128, 1), 256>>>(
        R, pT, pRW, NR, 200, 200, 200, 200, 200, 0.5f, 200);
    // outR = R @ w_rel  (fp16 MMA)
    hmma_gemm_k<float, float, false><<<dim3(2, (NR + 127) / 128, 1), 256>>>(
        R, w_rel, pOutR, NR, 200, 200, 200, 200, 200, 1.f, 200);
    // EP = E @ comb  (fp16 MMA, fp16 out — the big precompute GEMM)
    hmma_gemm_k<float, __half, false><<<dim3(11, (Ntot + 127) / 128, 1), 256>>>(
        E, pComb, pEP, Ntot, 1400, 200, 200, CPITCH, CPITCH, 1.f, 200);
    // hembW: gather-sum per hyperedge (fp32 accum, fp16 store)
    hembw_k<<<(H * 50 + 255) / 256, 256>>>(hyperedge, H);
    // per-edge scatter (fp16 gathers, fp32 vector RED)
    edge_k<<<(NEdge * 50 + 255) / 256, 256>>>(edge_index, edge_type, NEdge);
    // outE = tanh(bn(0.5*agg + 0.5*E))
    oute_k<<<(Ntot * 50 + 255) / 256, 256>>>(E, bnmp_g, bnmp_b, Ntot);
    // Y = relu(bn1(conv(bn0(stack)))) -> fp16
    buildY_k<<<Bsz, 256>>>(ms, r_idx, ip, conv_w, conv_b,
                           bn0_g, bn0_b, bn1_g, bn1_b, ent);
    // FCACC += Y @ fc_w  (fp16 MMA, split-K 25 x 1584 = 99 full k16 iters)
    hmma_gemm_k<__half, float, true><<<dim3(2, (Bsz + 127) / 128, 25), 256>>>(
        pY, fc_w, pFC, Bsz, 200, FEATK, FEATK, 200, 200, 1.f, 1584);
    // out[b] = sum_d relu(bn2(FCACC + fc_b))
    final_k<<<(Bsz * 32 + 255) / 256, 256>>>(fc_b, bn2_g, bn2_b,
                                             (float*)d_out, Bsz);
}

// round 8
// speedup vs baseline: 2.8466x; 1.0668x over previous
#include <cuda_runtime.h>
#include <cuda_fp16.h>
#include <math.h>

// BN scale: 1/sqrt(1 + 1e-5)
#define BNS 0.9999950000374997f

#define DD      200
#define NTOT_MX 50006
#define H_MX    100000
#define NE_MX   600000
#define B_MX    2048
#define NR_MX   2048
#define CPITCH  1408      // EP row pitch (halves)
#define FEATK   39600     // 200 * 198

// ---------------- static device scratch ----------------------------------
__device__ __align__(128) float  g_T[200 * 200];
__device__ __align__(128) float  g_U[1200 * 200];
__device__ __align__(128) __half g_combh[200 * CPITCH];
__device__ __align__(128) __half g_Wcat[200 * 400];   // [0.5*T | w_rel] fp16
__device__ __align__(128) float  g_RO[(size_t)NR_MX * 400]; // [RW | outR]
__device__ __align__(128) __half g_Eh[(size_t)NTOT_MX * 200];
__device__ __align__(128) __half g_Rh[(size_t)NR_MX * 200];
__device__ __align__(128) __half g_fcwh[(size_t)FEATK * 200];
__device__ __align__(128) __half g_EP[(size_t)NTOT_MX * CPITCH];
__device__ __align__(128) __half g_hembW[(size_t)H_MX * 200];
__device__ __align__(128) float  g_agg[(size_t)NTOT_MX * 200];
__device__ __align__(128) float  g_outE[(size_t)NTOT_MX * 200];
__device__ __align__(128) __half g_Y[(size_t)B_MX * FEATK];
__device__ __align__(128) float  g_FCACC[(size_t)B_MX * 200];

// ---------------- helpers -------------------------------------------------
__device__ __forceinline__ unsigned pack2(float a, float b) {
    __half2 h = __floats2half2_rn(a, b);
    return *(unsigned*)&h;
}
__device__ __forceinline__ void red2(float* p, float x, float y) {
    asm volatile("red.global.add.v2.f32 [%0], {%1, %2};"
                 :: "l"(p), "f"(x), "f"(y) : "memory");
}
__device__ __forceinline__ float4 ld4(const float* p) {
    return *(const float4*)p;
}
__device__ __forceinline__ float4 ld4(const __half* p) {
    uint2 u = *(const uint2*)p;
    __half2 h0 = *(__half2*)&u.x;
    __half2 h1 = *(__half2*)&u.y;
    float2 a = __half22float2(h0);
    float2 b = __half22float2(h1);
    return make_float4(a.x, a.y, b.x, b.y);
}
__device__ __forceinline__ void store2(float* p, float x, float y) {
    *(float2*)p = make_float2(x, y);
}
__device__ __forceinline__ void store2(__half* p, float x, float y) {
    *(__half2*)p = __floats2half2_rn(x, y);
}
// 8 consecutive A elements -> 4 packed half2 words
__device__ __forceinline__ uint4 ldA8(const float* p) {
    float4 x = *(const float4*)p;
    float4 y = *(const float4*)(p + 4);
    uint4 r;
    r.x = pack2(x.x, x.y); r.y = pack2(x.z, x.w);
    r.z = pack2(y.x, y.y); r.w = pack2(y.z, y.w);
    return r;
}
__device__ __forceinline__ uint4 ldA8(const __half* p) {
    return *(const uint4*)p;
}
// 2 consecutive A elements -> packed half2 (k8 tail)
__device__ __forceinline__ unsigned ldA2(const float* p) {
    float2 v = *(const float2*)p;
    return pack2(v.x, v.y);
}
__device__ __forceinline__ unsigned ldA2(const __half* p) {
    return *(const unsigned*)p;
}
// scalar B element (k8 tail)
__device__ __forceinline__ float ldS(const float* p) { return *p; }
__device__ __forceinline__ float ldS(const __half* p) { return __half2float(*p); }

// B fragment loader: 4 rows (0,1,8,9)*ldb x 2 cols -> 4 packed k-pair words
__device__ __forceinline__ void loadBfrag(const float* q, int ldb, unsigned* bS) {
    float2 r0a = *(const float2*)(q);
    float2 r0b = *(const float2*)(q + (size_t)ldb);
    float2 r1a = *(const float2*)(q + (size_t)8 * ldb);
    float2 r1b = *(const float2*)(q + (size_t)9 * ldb);
    bS[0] = pack2(r0a.x, r0b.x);
    bS[1] = pack2(r1a.x, r1b.x);
    bS[2] = pack2(r0a.y, r0b.y);
    bS[3] = pack2(r1a.y, r1b.y);
}
__device__ __forceinline__ void loadBfrag(const __half* q, int ldb, unsigned* bS) {
    __half2 r0a = *(const __half2*)(q);
    __half2 r0b = *(const __half2*)(q + (size_t)ldb);
    __half2 r1a = *(const __half2*)(q + (size_t)8 * ldb);
    __half2 r1b = *(const __half2*)(q + (size_t)9 * ldb);
    __half2 t;
    t = __halves2half2(__low2half(r0a),  __low2half(r0b));  bS[0] = *(unsigned*)&t;
    t = __halves2half2(__low2half(r1a),  __low2half(r1b));  bS[1] = *(unsigned*)&t;
    t = __halves2half2(__high2half(r0a), __high2half(r0b)); bS[2] = *(unsigned*)&t;
    t = __halves2half2(__high2half(r1a), __high2half(r1b)); bS[3] = *(unsigned*)&t;
}

__device__ __forceinline__ void mma_f16_k16(float* c, const unsigned* a,
                                            const unsigned* b) {
    asm volatile(
        "mma.sync.aligned.m16n8k16.row.col.f32.f16.f16.f32 "
        "{%0,%1,%2,%3}, {%4,%5,%6,%7}, {%8,%9}, {%0,%1,%2,%3};"
        : "+f"(c[0]), "+f"(c[1]), "+f"(c[2]), "+f"(c[3])
        : "r"(a[0]), "r"(a[1]), "r"(a[2]), "r"(a[3]), "r"(b[0]), "r"(b[1]));
}
__device__ __forceinline__ void mma_f16_k8(float* c, const unsigned* a,
                                           unsigned b) {
    asm volatile(
        "mma.sync.aligned.m16n8k8.row.col.f32.f16.f16.f32 "
        "{%0,%1,%2,%3}, {%4,%5}, {%6}, {%0,%1,%2,%3};"
        : "+f"(c[0]), "+f"(c[1]), "+f"(c[2]), "+f"(c[3])
        : "r"(a[0]), "r"(a[1]), "r"(b));
}

// =========================================================================
// fp16 tensor-core GEMM (fp32 accum): C = alpha * A(MxK,row) @ B(KxN,row)
// Block 128x128, BK=16, 256 threads (8 warps 2x4), warp tile 64x32,
// mma.sync.m16n8k16. Double-buffered fragment-order smem.
// kChunk: multiple of 8 (a k8 tail handles kChunk%16==8). N multiple of 2.
// =========================================================================
template <class AT, class BT, class CT, bool ATOMIC>
__global__ void __launch_bounds__(256, 2) hmma_gemm_k(
    const AT* __restrict__ A, const BT* __restrict__ B,
    CT* __restrict__ C, int M, int N, int K,
    int lda, int ldb, int ldc, float alpha, int kChunk)
{
    __shared__ __align__(16) unsigned As[2][1024];
    __shared__ __align__(16) unsigned Bs[2][1056];

    const int tid  = threadIdx.x;
    const int lane = tid & 31;
    const int warp = tid >> 5;
    const int wm = warp >> 2;
    const int wn = warp & 3;
    const int m0 = blockIdx.y * 128;
    const int n0b = blockIdx.x * 128;

    const int kBegin = blockIdx.z * kChunk;
    const int kEnd   = min(kBegin + kChunk, K);
    const int iters  = (kEnd - kBegin) >> 4;
    const bool tail8 = ((kEnd - kBegin) & 8) != 0;

    // ---- A loader: thread -> (row am, k-half khalf)
    const int am    = tid >> 1;
    const int khalf = tid & 1;
    const bool aVal = (m0 + am) < M;
    const AT* Ap = A + (size_t)(m0 + am) * lda + kBegin + khalf * 8;
    const int amf  = am >> 4;
    const int ar   = am & 15;
    const int arl  = ar & 7;
    const int aReg = (khalf << 1) | (ar >> 3);

    // ---- B loader: thread -> (k-pair bkp, 2 cols bn0)
    const int bkp = (tid >> 6) & 3;
    const int bn0 = (tid & 63) << 1;
    const bool bVal = (n0b + bn0) < N;
    const BT* Bp = B + (size_t)(kBegin + 2 * bkp) * ldb + n0b + bn0;
    const int bnf = bn0 >> 3;
    const int bLane0 = (bn0 & 7) * 4 + bkp;

    float acc[4][4][4];
#pragma unroll
    for (int i = 0; i < 4; i++)
#pragma unroll
        for (int j = 0; j < 4; j++)
#pragma unroll
            for (int q = 0; q < 4; q++) acc[i][j][q] = 0.f;

    uint4 aS;
    unsigned bS[4];

#define LOAD_TILE(IT)                                                        \
    {                                                                        \
        aS = make_uint4(0u, 0u, 0u, 0u);                                     \
        if (aVal) aS = ldA8(Ap + ((IT) << 4));                               \
        if (bVal) loadBfrag(Bp + (size_t)((IT) << 4) * ldb, ldb, bS);        \
        else { bS[0] = bS[1] = bS[2] = bS[3] = 0u; }                         \
    }
#define STORE_TILE(BUF)                                                      \
    {                                                                        \
        unsigned aw[4] = {aS.x, aS.y, aS.z, aS.w};                           \
        _Pragma("unroll")                                                    \
        for (int jj = 0; jj < 4; jj++) {                                     \
            int c_   = arl * 4 + jj;                                         \
            int phys = c_ ^ ((c_ >> 3) & 3);                                 \
            As[BUF][amf * 128 + phys * 4 + aReg] = aw[jj];                   \
        }                                                                    \
        Bs[BUF][bnf * 66 + bLane0 * 2 + 0]       = bS[0];                    \
        Bs[BUF][bnf * 66 + bLane0 * 2 + 1]       = bS[1];                    \
        Bs[BUF][bnf * 66 + (bLane0 + 4) * 2 + 0] = bS[2];                    \
        Bs[BUF][bnf * 66 + (bLane0 + 4) * 2 + 1] = bS[3];                    \
    }

    const int lphys = lane ^ ((lane >> 3) & 3);

    if (iters > 0) {
        LOAD_TILE(0);
        STORE_TILE(0);
        __syncthreads();
    }

    for (int it = 0; it < iters; ++it) {
        const int cur = it & 1;
        if (it + 1 < iters) LOAD_TILE(it + 1);

        unsigned af[4][4], bf[4][2];
#pragma unroll
        for (int mf = 0; mf < 4; mf++) {
            uint4 t = *(const uint4*)&As[cur][(wm * 4 + mf) * 128 + lphys * 4];
            af[mf][0] = t.x; af[mf][1] = t.y; af[mf][2] = t.z; af[mf][3] = t.w;
        }
#pragma unroll
        for (int nf = 0; nf < 4; nf++) {
            uint2 t = *(const uint2*)&Bs[cur][(wn * 4 + nf) * 66 + lane * 2];
            bf[nf][0] = t.x; bf[nf][1] = t.y;
        }
#pragma unroll
        for (int mf = 0; mf < 4; mf++)
#pragma unroll
            for (int nf = 0; nf < 4; nf++)
                mma_f16_k16(acc[mf][nf], af[mf], bf[nf]);

        if (it + 1 < iters) {
            STORE_TILE(cur ^ 1);
            __syncthreads();
        }
    }
#undef LOAD_TILE
#undef STORE_TILE

    // ---- k8 tail (direct from global)
    if (tail8) {
        const int kT = kEnd - 8;
        const int kOff = kT + 2 * (lane & 3);
        unsigned bt[4];
#pragma unroll
        for (int nf = 0; nf < 4; nf++) {
            int col = n0b + wn * 32 + nf * 8 + (lane >> 2);
            float v0 = 0.f, v1 = 0.f;
            if (col < N) {
                v0 = ldS(B + (size_t)kOff * ldb + col);
                v1 = ldS(B + (size_t)(kOff + 1) * ldb + col);
            }
            bt[nf] = pack2(v0, v1);
        }
#pragma unroll
        for (int mf = 0; mf < 4; mf++) {
            int r0 = m0 + wm * 64 + mf * 16 + (lane >> 2);
            unsigned at[2];
            at[0] = (r0 < M)     ? ldA2(A + (size_t)r0 * lda + kOff)       : 0u;
            at[1] = (r0 + 8 < M) ? ldA2(A + (size_t)(r0 + 8) * lda + kOff) : 0u;
#pragma unroll
            for (int nf = 0; nf < 4; nf++)
                mma_f16_k8(acc[mf][nf], at, bt[nf]);
        }
    }

    // ---- epilogue
#pragma unroll
    for (int mf = 0; mf < 4; mf++) {
#pragma unroll
        for (int nf = 0; nf < 4; nf++) {
            int row = m0 + wm * 64 + mf * 16 + (lane >> 2);
            int col = n0b + wn * 32 + nf * 8 + ((lane & 3) << 1);
            if (col >= N) continue;
            CT* p = C + (size_t)row * ldc + col;
            if (row < M) {
                if (ATOMIC) red2((float*)(void*)p,
                                 alpha * acc[mf][nf][0], alpha * acc[mf][nf][1]);
                else store2(p, alpha * acc[mf][nf][0], alpha * acc[mf][nf][1]);
            }
            if (row + 8 < M) {
                CT* q = p + (size_t)8 * ldc;
                if (ATOMIC) red2((float*)(void*)q,
                                 alpha * acc[mf][nf][2], alpha * acc[mf][nf][3]);
                else store2(q, alpha * acc[mf][nf][2], alpha * acc[mf][nf][3]);
            }
        }
    }
}

// ---------------- SIMT SGEMM (exact fp32) for the weight precompute ------
template <bool ATOMIC>
__global__ void __launch_bounds__(256) sgemm_k(
    const float* __restrict__ A, const float* __restrict__ B,
    float* __restrict__ C, int M, int Ncols, int K,
    int lda, int ldb, int ldc, float alpha, int kChunk)
{
    __shared__ float As[8][128];
    __shared__ float Bs[8][128];

    const int tid = threadIdx.x;
    const int tx = tid & 15;
    const int ty = tid >> 4;
    const int m0 = blockIdx.y * 128;
    const int n0 = blockIdx.x * 128;

    int kBegin = blockIdx.z * kChunk;
    int kEnd = kBegin + kChunk;
    if (kEnd > K) kEnd = K;

    const int aRow = tid >> 1;
    const int aK4  = (tid & 1) << 2;
    const int bRow = tid >> 5;
    const int bCol = (tid & 31) << 2;

    float acc[8][8];
#pragma unroll
    for (int i = 0; i < 8; i++)
#pragma unroll
        for (int j = 0; j < 8; j++) acc[i][j] = 0.f;

    for (int k0 = kBegin; k0 < kEnd; k0 += 8) {
        float4 av = make_float4(0.f, 0.f, 0.f, 0.f);
        if (m0 + aRow < M)
            av = *(const float4*)(A + (size_t)(m0 + aRow) * lda + (k0 + aK4));
        As[aK4 + 0][aRow] = av.x;
        As[aK4 + 1][aRow] = av.y;
        As[aK4 + 2][aRow] = av.z;
        As[aK4 + 3][aRow] = av.w;

        float4 bv = make_float4(0.f, 0.f, 0.f, 0.f);
        if (n0 + bCol < Ncols)
            bv = *(const float4*)(B + (size_t)(k0 + bRow) * ldb + (n0 + bCol));
        *(float4*)&Bs[bRow][bCol] = bv;

        __syncthreads();
#pragma unroll
        for (int kk = 0; kk < 8; kk++) {
            float ar[8], br[8];
#pragma unroll
            for (int i = 0; i < 8; i++) ar[i] = As[kk][ty * 8 + i];
#pragma unroll
            for (int j = 0; j < 8; j++) br[j] = Bs[kk][tx * 8 + j];
#pragma unroll
            for (int i = 0; i < 8; i++)
#pragma unroll
                for (int j = 0; j < 8; j++)
                    acc[i][j] = fmaf(ar[i], br[j], acc[i][j]);
        }
        __syncthreads();
    }

#pragma unroll
    for (int i = 0; i < 8; i++) {
        int m = m0 + ty * 8 + i;
        if (m >= M) continue;
        if (ATOMIC) {
#pragma unroll
            for (int jj = 0; jj < 8; jj += 2) {
                int n = n0 + tx * 8 + jj;
                if (n < Ncols)
                    red2(C + (size_t)m * ldc + n,
                         alpha * acc[i][jj], alpha * acc[i][jj + 1]);
            }
        } else {
#pragma unroll
            for (int jj = 0; jj < 8; jj += 4) {
                int n = n0 + tx * 8 + jj;
                if (n < Ncols) {
                    float4 v = make_float4(alpha * acc[i][jj + 0],
                                           alpha * acc[i][jj + 1],
                                           alpha * acc[i][jj + 2],
                                           alpha * acc[i][jj + 3]);
                    *(float4*)(C + (size_t)m * ldc + n) = v;
                }
            }
        }
    }
}

// ---------------- fp32 -> fp16 bulk convert (n4 = elems/4) ---------------
__global__ void f2h_k(const float* __restrict__ s, __half* __restrict__ d,
                      int n4)
{
    int i = blockIdx.x * 256 + threadIdx.x;
    if (i >= n4) return;
    float4 v = ((const float4*)s)[i];
    uint2 o;
    o.x = pack2(v.x, v.y);
    o.y = pack2(v.z, v.w);
    ((uint2*)d)[i] = o;
}

// ---------------- build fused weight comb (200 x 1400, fp16) -------------
__global__ void build_comb_k(const float* __restrict__ E,
                             const float* __restrict__ w_addpos, int ent)
{
    int idx = blockIdx.x * 256 + threadIdx.x;
    if (idx >= 200 * 1400) return;
    int i = idx / 1400;
    int c = idx - i * 1400;
    float v;
    if (c < 1200) {
        int k = c / 200;
        int j = c - k * 200;
        v = 0.5f * E[(size_t)(ent + k) * DD + i] *
            g_U[(size_t)(k * 200 + i) * 200 + j];
    } else {
        v = w_addpos[(size_t)(200 + i) * 200 + (c - 1200)];
    }
    g_combh[(size_t)i * CPITCH + c] = __float2half(v);
}

// ---------------- build Wcat = [0.5*T | w_rel] fp16 (200 x 400) ----------
__global__ void wcat_k(const float* __restrict__ w_rel)
{
    int idx = blockIdx.x * 256 + threadIdx.x;
    if (idx >= 200 * 400) return;
    int i = idx / 400;
    int c = idx - i * 400;
    float v = (c < 200) ? 0.5f * g_T[i * 200 + c]
                        : w_rel[(size_t)i * 200 + (c - 200)];
    g_Wcat[idx] = __float2half(v);
}

// ---------------- hembW[h] = RO[he0,0:200] + sum_k EP[he_k+1, k*200:] ----
__global__ void hembw_k(const int* __restrict__ he, int H)
{
    int t = blockIdx.x * 256 + threadIdx.x;
    int h = t / 50;
    int c = t - h * 50;
    if (h >= H) return;
    const int* row = he + (size_t)h * 7;
    int r = row[0];
    float4 acc = *(const float4*)(g_RO + (size_t)r * 400 + c * 4);
#pragma unroll
    for (int k = 0; k < 6; k++) {
        int e = row[1 + k];
        float4 v = ld4(g_EP + (size_t)e * CPITCH + k * 200 + c * 4);
        acc.x += v.x; acc.y += v.y; acc.z += v.z; acc.w += v.w;
    }
    __half* dst = g_hembW + (size_t)h * 200 + c * 4;
    ((__half2*)dst)[0] = __floats2half2_rn(acc.x, acc.y);
    ((__half2*)dst)[1] = __floats2half2_rn(acc.z, acc.w);
}

// ---------------- per-edge scatter: agg[seg] += hembW[et] + EP[gidx] -----
__global__ void edge_k(const int* __restrict__ ei,
                       const int* __restrict__ et, int NEdge)
{
    int t = blockIdx.x * 256 + threadIdx.x;
    int e = t / 50;
    int c = t - e * 50;
    if (e >= NEdge) return;
    int seg  = ei[e];
    int gidx = ei[NEdge + e];
    int h    = et[e];
    float4 a = ld4(g_hembW + (size_t)h * 200 + c * 4);
    float4 b = ld4(g_EP + (size_t)gidx * CPITCH + 1200 + c * 4);
    float* p = g_agg + (size_t)seg * 200 + c * 4;
    asm volatile("red.global.add.v4.f32 [%0], {%1, %2, %3, %4};"
                 :: "l"(p), "f"(a.x + b.x), "f"(a.y + b.y),
                    "f"(a.z + b.z), "f"(a.w + b.w) : "memory");
}

// ---------------- outE = tanh(bn(0.5*agg + 0.5*E)) -----------------------
__global__ void oute_k(const float* __restrict__ E,
                       const float* __restrict__ g,
                       const float* __restrict__ bb, int Ntot)
{
    int t = blockIdx.x * 256 + threadIdx.x;
    int n = t / 50;
    int c = t - n * 50;
    if (n >= Ntot) return;
    size_t off = (size_t)n * 200 + c * 4;
    float4 e = *(const float4*)(E + off);
    float4 a = *(const float4*)(g_agg + off);
    int d = c * 4;
    float4 o;
    o.x = tanhf(0.5f * (a.x + e.x) * (g[d + 0] * BNS) + bb[d + 0]);
    o.y = tanhf(0.5f * (a.y + e.y) * (g[d + 1] * BNS) + bb[d + 1]);
    o.z = tanhf(0.5f * (a.z + e.z) * (g[d + 2] * BNS) + bb[d + 2]);
    o.w = tanhf(0.5f * (a.w + e.w) * (g[d + 3] * BNS) + bb[d + 3]);
    *(float4*)(g_outE + off) = o;
}

// ---------------- fused stack + bn0 + conv7x3 + bn1 + relu -> Y (fp16) ---
struct IdxPtrs { const int* p[6]; };

__global__ void __launch_bounds__(256) buildY_k(
    const float* __restrict__ ms, const int* __restrict__ r_idx, IdxPtrs ip,
    const float* __restrict__ conv_w, const float* __restrict__ conv_b,
    const float* __restrict__ bn0_g, const float* __restrict__ bn0_b,
    const float* __restrict__ bn1_g, const float* __restrict__ bn1_b,
    int ent)
{
    __shared__ float xs[7][204];
    __shared__ float cw[4200];

    int b = blockIdx.x;
    int t = threadIdx.x;

    for (int i = t; i < 4200; i += 256) cw[i] = conv_w[i];
    if (t < 28) xs[t >> 2][200 + (t & 3)] = 0.f;

    float g0 = bn0_g[0] * BNS;
    float b0 = bn0_b[0];
    int ri = r_idx[b];

    for (int idx = t; idx < 1400; idx += 256) {
        int i = idx / 200;
        int d = idx - i * 200;
        float v;
        if (i == 0) {
            v = g_RO[(size_t)ri * 400 + 200 + d];
        } else {
            int k = i - 1;
            int eidx = ip.p[k][b];
            v = g_outE[(size_t)eidx * 200 + d] *
                g_outE[(size_t)(ent + k) * 200 + d] * ms[b * 6 + k];
        }
        xs[i][d] = v * g0 + b0;
    }
    __syncthreads();

    __half* ybase = g_Y + (size_t)b * FEATK;
    for (int it = t; it < 5000; it += 256) {
        int nf = it / 25;
        int pg = it - nf * 25;
        int p0 = pg * 8;
        float w[21];
#pragma unroll
        for (int q = 0; q < 21; q++) w[q] = cw[nf * 21 + q];
        float acc[8];
#pragma unroll
        for (int q = 0; q < 8; q++) acc[q] = 0.f;
#pragma unroll
        for (int i = 0; i < 7; i++) {
            float x[10];
#pragma unroll
            for (int q = 0; q < 10; q++) x[q] = xs[i][p0 + q];
#pragma unroll
            for (int q = 0; q < 8; q++)
                acc[q] += x[q] * w[i * 3 + 0] + x[q + 1] * w[i * 3 + 1] +
                          x[q + 2] * w[i * 3 + 2];
        }
        float cb = conv_b[nf];
        float g1 = bn1_g[nf] * BNS;
        float b1 = bn1_b[nf];
        __half* yr = ybase + nf * 198 + p0;
        int lim = min(198 - p0, 8);
#pragma unroll
        for (int q = 0; q < 8; q += 2) {
            if (q < lim) {
                float v0 = fmaxf((acc[q + 0] + cb) * g1 + b1, 0.f);
                float v1 = fmaxf((acc[q + 1] + cb) * g1 + b1, 0.f);
                *(__half2*)(yr + q) = __floats2half2_rn(v0, v1);
            }
        }
    }
}

// ---------------- final: relu(bn2(fc + bias)) row-sum -> out[b] ----------
__global__ void final_k(const float* __restrict__ fc_b,
                        const float* __restrict__ g,
                        const float* __restrict__ bb,
                        float* __restrict__ out, int B)
{
    int gt = blockIdx.x * 256 + threadIdx.x;
    int wb = gt >> 5;
    int lane = gt & 31;
    if (wb >= B) return;
    float s = 0.f;
    for (int d = lane; d < 200; d += 32) {
        float v = (g_FCACC[(size_t)wb * 200 + d] + fc_b[d]) * (g[d] * BNS) + bb[d];
        s += fmaxf(v, 0.f);
    }
#pragma unroll
    for (int o = 16; o; o >>= 1) s += __shfl_down_sync(0xffffffffu, s, o);
    if (lane == 0) out[wb] = s;
}

// ---------------- host orchestration ------------------------------------
extern "C" void kernel_launch(void* const* d_in, const int* in_sizes, int n_in,
                              void* d_out, int out_size)
{
    const float* E          = (const float*)d_in[0];
    const float* R          = (const float*)d_in[1];
    const float* w_alle     = (const float*)d_in[2];
    const float* w_addpos   = (const float*)d_in[3];
    const float* w_alleandr = (const float*)d_in[4];
    const float* w_rel      = (const float*)d_in[5];
    const float* conv_w     = (const float*)d_in[6];
    const float* conv_b     = (const float*)d_in[7];
    const float* fc_w       = (const float*)d_in[8];
    const float* fc_b       = (const float*)d_in[9];
    const float* bnmp_g     = (const float*)d_in[10];
    const float* bnmp_b     = (const float*)d_in[11];
    const float* bn0_g      = (const float*)d_in[12];
    const float* bn0_b      = (const float*)d_in[13];
    const float* bn1_g      = (const float*)d_in[14];
    const float* bn1_b      = (const float*)d_in[15];
    const float* bn2_g      = (const float*)d_in[16];
    const float* bn2_b      = (const float*)d_in[17];
    const float* ms         = (const float*)d_in[18];
    const int*   hyperedge  = (const int*)d_in[19];
    const int*   edge_index = (const int*)d_in[20];
    const int*   edge_type  = (const int*)d_in[21];
    const int*   r_idx      = (const int*)d_in[22];
    IdxPtrs ip;
    for (int k = 0; k < 6; k++) ip.p[k] = (const int*)d_in[23 + k];

    const int Ntot  = in_sizes[0] / DD;   // 50006
    const int ent   = Ntot - 6;
    const int NR    = in_sizes[1] / DD;   // 2000
    const int H     = in_sizes[19] / 7;   // 100000
    const int NEdge = in_sizes[21];       // 600000
    const int Bsz   = in_sizes[22];       // 2048

    float *pT, *pU, *pRO, *pAgg, *pFC;
    __half *pComb, *pWcat, *pEh, *pRh, *pFcw, *pEP, *pY;
    cudaGetSymbolAddress((void**)&pT,    g_T);
    cudaGetSymbolAddress((void**)&pU,    g_U);
    cudaGetSymbolAddress((void**)&pComb, g_combh);
    cudaGetSymbolAddress((void**)&pWcat, g_Wcat);
    cudaGetSymbolAddress((void**)&pRO,   g_RO);
    cudaGetSymbolAddress((void**)&pEh,   g_Eh);
    cudaGetSymbolAddress((void**)&pRh,   g_Rh);
    cudaGetSymbolAddress((void**)&pFcw,  g_fcwh);
    cudaGetSymbolAddress((void**)&pEP,   g_EP);
    cudaGetSymbolAddress((void**)&pAgg,  g_agg);
    cudaGetSymbolAddress((void**)&pY,    g_Y);
    cudaGetSymbolAddress((void**)&pFC,   g_FCACC);

    cudaMemsetAsync(pT,   0, 200 * 200 * sizeof(float), 0);
    cudaMemsetAsync(pU,   0, 1200 * 200 * sizeof(float), 0);
    cudaMemsetAsync(pAgg, 0, (size_t)Ntot * 200 * sizeof(float), 0);
    cudaMemsetAsync(pFC,  0, (size_t)Bsz * 200 * sizeof(float), 0);

    // fp16 pre-conversions (identical rounding point as in-loop cvt)
    {
        int n4e = Ntot * DD / 4;
        f2h_k<<<(n4e + 255) / 256, 256>>>(E, pEh, n4e);
        int n4w = FEATK * DD / 4;
        f2h_k<<<(n4w + 255) / 256, 256>>>(fc_w, pFcw, n4w);
        int n4r = NR * DD / 4;
        f2h_k<<<(n4r + 255) / 256, 256>>>(R, pRh, n4r);
    }

    // T = w_alleandr @ w_addpos_top  (exact fp32, split-K)
    sgemm_k<true><<<dim3(2, 2, 13), 256>>>(w_alleandr, w_addpos, pT,
                                           200, 200, 200, 200, 200, 200, 1.f, 16);
    // U = w_alle @ T  (exact fp32)
    sgemm_k<true><<<dim3(2, 10, 5), 256>>>(w_alle, pT, pU,
                                           1200, 200, 200, 200, 200, 200, 1.f, 40);
    // comb (200 x 1400, fp16)
    build_comb_k<<<(200 * 1400 + 255) / 256, 256>>>(E, w_addpos, ent);
    // Wcat = [0.5*T | w_rel] fp16
    wcat_k<<<(200 * 400 + 255) / 256, 256>>>(w_rel);
    // RO = Rh @ Wcat  (fp16 MMA; cols 0..199 = RW, 200..399 = outR)
    hmma_gemm_k<__half, __half, float, false>
        <<<dim3(4, (NR + 127) / 128, 1), 256>>>(
        pRh, pWcat, pRO, NR, 400, 200, 200, 400, 400, 1.f, 200);
    // EP = Eh @ comb  (fp16 MMA, fp16 out — the big precompute GEMM)
    hmma_gemm_k<__half, __half, __half, false>
        <<<dim3(11, (Ntot + 127) / 128, 1), 256>>>(
        pEh, pComb, pEP, Ntot, 1400, 200, 200, CPITCH, CPITCH, 1.f, 200);
    // hembW: gather-sum per hyperedge (fp32 accum, fp16 store)
    hembw_k<<<(H * 50 + 255) / 256, 256>>>(hyperedge, H);
    // per-edge scatter (fp16 gathers, fp32 vector RED)
    edge_k<<<(NEdge * 50 + 255) / 256, 256>>>(edge_index, edge_type, NEdge);
    // outE = tanh(bn(0.5*agg + 0.5*E))
    oute_k<<<(Ntot * 50 + 255) / 256, 256>>>(E, bnmp_g, bnmp_b, Ntot);
    // Y = relu(bn1(conv(bn0(stack)))) -> fp16
    buildY_k<<<Bsz, 256>>>(ms, r_idx, ip, conv_w, conv_b,
                           bn0_g, bn0_b, bn1_g, bn1_b, ent);
    // FCACC += Y @ fcwh  (fp16 MMA, split-K 25 x 1584)
    hmma_gemm_k<__half, __half, float, true>
        <<<dim3(2, (Bsz + 127) / 128, 25), 256>>>(
        pY, pFcw, pFC, Bsz, 200, FEATK, FEATK, 200, 200, 1.f, 1584);
    // out[b] = sum_d relu(bn2(FCACC + fc_b))
    final_k<<<(Bsz * 32 + 255) / 256, 256>>>(fc_b, bn2_g, bn2_b,
                                             (float*)d_out, Bsz);
}

// round 9
// speedup vs baseline: 3.3895x; 1.1907x over previous
#include <cuda_runtime.h>
#include <cuda_fp16.h>
#include <math.h>

// BN scale: 1/sqrt(1 + 1e-5)
#define BNS 0.9999950000374997f

#define DD      200
#define NTOT_MX 50006
#define H_MX    100000
#define NE_MX   600000
#define B_MX    2048
#define NR_MX   2048
#define CPITCH  1408      // EP row pitch (halves)
#define FEATK   39600     // 200 * 198
#define MROWS   (B_MX * 198)   // im2col rows

// ---------------- static device scratch ----------------------------------
__device__ __align__(128) float  g_T[200 * 200];
__device__ __align__(128) float  g_U[1200 * 200];
__device__ __align__(128) __half g_combh[200 * CPITCH];
__device__ __align__(128) __half g_Wcat[200 * 400];   // [0.5*T | w_rel] fp16
__device__ __align__(128) float  g_RO[(size_t)NR_MX * 400]; // [RW | outR]
__device__ __align__(128) __half g_Eh[(size_t)NTOT_MX * 200];
__device__ __align__(128) __half g_Rh[(size_t)NR_MX * 200];
__device__ __align__(128) __half g_fcwh[(size_t)FEATK * 200]; // permuted (p,nf)
__device__ __align__(128) __half g_EP[(size_t)NTOT_MX * CPITCH];
__device__ __align__(128) __half g_hembW[(size_t)H_MX * 200];
__device__ __align__(128) float  g_agg[(size_t)NTOT_MX * 200];
__device__ __align__(128) float  g_outE[(size_t)NTOT_MX * 200];
__device__ __align__(128) __half g_X[(size_t)MROWS * 32];    // im2col, K pad 32
__device__ __align__(128) __half g_convW[32 * 200];          // conv W [k][nf]
__device__ __align__(128) float  g_epiG[256];
__device__ __align__(128) float  g_epiB[256];
__device__ __align__(128) __half g_Y[(size_t)B_MX * FEATK];  // (b)(p*200+nf)
__device__ __align__(128) float  g_FCACC[(size_t)B_MX * 200];

// ---------------- helpers -------------------------------------------------
__device__ __forceinline__ unsigned pack2(float a, float b) {
    __half2 h = __floats2half2_rn(a, b);
    return *(unsigned*)&h;
}
__device__ __forceinline__ void red2(float* p, float x, float y) {
    asm volatile("red.global.add.v2.f32 [%0], {%1, %2};"
                 :: "l"(p), "f"(x), "f"(y) : "memory");
}
__device__ __forceinline__ float4 ld4(const float* p) {
    return *(const float4*)p;
}
__device__ __forceinline__ float4 ld4(const __half* p) {
    uint2 u = *(const uint2*)p;
    __half2 h0 = *(__half2*)&u.x;
    __half2 h1 = *(__half2*)&u.y;
    float2 a = __half22float2(h0);
    float2 b = __half22float2(h1);
    return make_float4(a.x, a.y, b.x, b.y);
}
__device__ __forceinline__ void store2(float* p, float x, float y) {
    *(float2*)p = make_float2(x, y);
}
__device__ __forceinline__ void store2(__half* p, float x, float y) {
    *(__half2*)p = __floats2half2_rn(x, y);
}
__device__ __forceinline__ uint4 ldA8(const float* p) {
    float4 x = *(const float4*)p;
    float4 y = *(const float4*)(p + 4);
    uint4 r;
    r.x = pack2(x.x, x.y); r.y = pack2(x.z, x.w);
    r.z = pack2(y.x, y.y); r.w = pack2(y.z, y.w);
    return r;
}
__device__ __forceinline__ uint4 ldA8(const __half* p) {
    return *(const uint4*)p;
}
__device__ __forceinline__ unsigned ldA2(const float* p) {
    float2 v = *(const float2*)p;
    return pack2(v.x, v.y);
}
__device__ __forceinline__ unsigned ldA2(const __half* p) {
    return *(const unsigned*)p;
}
__device__ __forceinline__ float ldS(const float* p) { return *p; }
__device__ __forceinline__ float ldS(const __half* p) { return __half2float(*p); }

__device__ __forceinline__ void loadBfrag(const float* q, int ldb, unsigned* bS) {
    float2 r0a = *(const float2*)(q);
    float2 r0b = *(const float2*)(q + (size_t)ldb);
    float2 r1a = *(const float2*)(q + (size_t)8 * ldb);
    float2 r1b = *(const float2*)(q + (size_t)9 * ldb);
    bS[0] = pack2(r0a.x, r0b.x);
    bS[1] = pack2(r1a.x, r1b.x);
    bS[2] = pack2(r0a.y, r0b.y);
    bS[3] = pack2(r1a.y, r1b.y);
}
__device__ __forceinline__ void loadBfrag(const __half* q, int ldb, unsigned* bS) {
    __half2 r0a = *(const __half2*)(q);
    __half2 r0b = *(const __half2*)(q + (size_t)ldb);
    __half2 r1a = *(const __half2*)(q + (size_t)8 * ldb);
    __half2 r1b = *(const __half2*)(q + (size_t)9 * ldb);
    __half2 t;
    t = __halves2half2(__low2half(r0a),  __low2half(r0b));  bS[0] = *(unsigned*)&t;
    t = __halves2half2(__low2half(r1a),  __low2half(r1b));  bS[1] = *(unsigned*)&t;
    t = __halves2half2(__high2half(r0a), __high2half(r0b)); bS[2] = *(unsigned*)&t;
    t = __halves2half2(__high2half(r1a), __high2half(r1b)); bS[3] = *(unsigned*)&t;
}

__device__ __forceinline__ void mma_f16_k16(float* c, const unsigned* a,
                                            const unsigned* b) {
    asm volatile(
        "mma.sync.aligned.m16n8k16.row.col.f32.f16.f16.f32 "
        "{%0,%1,%2,%3}, {%4,%5,%6,%7}, {%8,%9}, {%0,%1,%2,%3};"
        : "+f"(c[0]), "+f"(c[1]), "+f"(c[2]), "+f"(c[3])
        : "r"(a[0]), "r"(a[1]), "r"(a[2]), "r"(a[3]), "r"(b[0]), "r"(b[1]));
}
__device__ __forceinline__ void mma_f16_k8(float* c, const unsigned* a,
                                           unsigned b) {
    asm volatile(
        "mma.sync.aligned.m16n8k8.row.col.f32.f16.f16.f32 "
        "{%0,%1,%2,%3}, {%4,%5}, {%6}, {%0,%1,%2,%3};"
        : "+f"(c[0]), "+f"(c[1]), "+f"(c[2]), "+f"(c[3])
        : "r"(a[0]), "r"(a[1]), "r"(b));
}

// =========================================================================
// fp16 tensor-core GEMM (fp32 accum): C = A(MxK,row) @ B(KxN,row)
// MODE 0: C = alpha*acc (store). MODE 1: red.global += alpha*acc.
// MODE 2: C = relu(acc * epiG[col] + epiB[col])  (conv bias+bn1 fused)
// Block 128x128, BK=16, 256 threads, warp tile 64x32, m16n8k16,
// double-buffered fragment-order smem. kChunk mult of 8 (k8 tail if %16==8).
// =========================================================================
template <class AT, class BT, class CT, int MODE>
__global__ void __launch_bounds__(256, 2) hmma_gemm_k(
    const AT* __restrict__ A, const BT* __restrict__ B,
    CT* __restrict__ C, int M, int N, int K,
    int lda, int ldb, int ldc, float alpha, int kChunk,
    const float* __restrict__ epiG, const float* __restrict__ epiB)
{
    __shared__ __align__(16) unsigned As[2][1024];
    __shared__ __align__(16) unsigned Bs[2][1056];

    const int tid  = threadIdx.x;
    const int lane = tid & 31;
    const int warp = tid >> 5;
    const int wm = warp >> 2;
    const int wn = warp & 3;
    const int m0 = blockIdx.y * 128;
    const int n0b = blockIdx.x * 128;

    const int kBegin = blockIdx.z * kChunk;
    const int kEnd   = min(kBegin + kChunk, K);
    const int iters  = (kEnd - kBegin) >> 4;
    const bool tail8 = ((kEnd - kBegin) & 8) != 0;

    const int am    = tid >> 1;
    const int khalf = tid & 1;
    const bool aVal = (m0 + am) < M;
    const AT* Ap = A + (size_t)(m0 + am) * lda + kBegin + khalf * 8;
    const int amf  = am >> 4;
    const int ar   = am & 15;
    const int arl  = ar & 7;
    const int aReg = (khalf << 1) | (ar >> 3);

    const int bkp = (tid >> 6) & 3;
    const int bn0 = (tid & 63) << 1;
    const bool bVal = (n0b + bn0) < N;
    const BT* Bp = B + (size_t)(kBegin + 2 * bkp) * ldb + n0b + bn0;
    const int bnf = bn0 >> 3;
    const int bLane0 = (bn0 & 7) * 4 + bkp;

    float acc[4][4][4];
#pragma unroll
    for (int i = 0; i < 4; i++)
#pragma unroll
        for (int j = 0; j < 4; j++)
#pragma unroll
            for (int q = 0; q < 4; q++) acc[i][j][q] = 0.f;

    uint4 aS;
    unsigned bS[4];

#define LOAD_TILE(IT)                                                        \
    {                                                                        \
        aS = make_uint4(0u, 0u, 0u, 0u);                                     \
        if (aVal) aS = ldA8(Ap + ((IT) << 4));                               \
        if (bVal) loadBfrag(Bp + (size_t)((IT) << 4) * ldb, ldb, bS);        \
        else { bS[0] = bS[1] = bS[2] = bS[3] = 0u; }                         \
    }
#define STORE_TILE(BUF)                                                      \
    {                                                                        \
        unsigned aw[4] = {aS.x, aS.y, aS.z, aS.w};                           \
        _Pragma("unroll")                                                    \
        for (int jj = 0; jj < 4; jj++) {                                     \
            int c_   = arl * 4 + jj;                                         \
            int phys = c_ ^ ((c_ >> 3) & 3);                                 \
            As[BUF][amf * 128 + phys * 4 + aReg] = aw[jj];                   \
        }                                                                    \
        Bs[BUF][bnf * 66 + bLane0 * 2 + 0]       = bS[0];                    \
        Bs[BUF][bnf * 66 + bLane0 * 2 + 1]       = bS[1];                    \
        Bs[BUF][bnf * 66 + (bLane0 + 4) * 2 + 0] = bS[2];                    \
        Bs[BUF][bnf * 66 + (bLane0 + 4) * 2 + 1] = bS[3];                    \
    }

    const int lphys = lane ^ ((lane >> 3) & 3);

    if (iters > 0) {
        LOAD_TILE(0);
        STORE_TILE(0);
        __syncthreads();
    }

    for (int it = 0; it < iters; ++it) {
        const int cur = it & 1;
        if (it + 1 < iters) LOAD_TILE(it + 1);

        unsigned af[4][4], bf[4][2];
#pragma unroll
        for (int mf = 0; mf < 4; mf++) {
            uint4 t = *(const uint4*)&As[cur][(wm * 4 + mf) * 128 + lphys * 4];
            af[mf][0] = t.x; af[mf][1] = t.y; af[mf][2] = t.z; af[mf][3] = t.w;
        }
#pragma unroll
        for (int nf = 0; nf < 4; nf++) {
            uint2 t = *(const uint2*)&Bs[cur][(wn * 4 + nf) * 66 + lane * 2];
            bf[nf][0] = t.x; bf[nf][1] = t.y;
        }
#pragma unroll
        for (int mf = 0; mf < 4; mf++)
#pragma unroll
            for (int nf = 0; nf < 4; nf++)
                mma_f16_k16(acc[mf][nf], af[mf], bf[nf]);

        if (it + 1 < iters) {
            STORE_TILE(cur ^ 1);
            __syncthreads();
        }
    }
#undef LOAD_TILE
#undef STORE_TILE

    if (tail8) {
        const int kT = kEnd - 8;
        const int kOff = kT + 2 * (lane & 3);
        unsigned bt[4];
#pragma unroll
        for (int nf = 0; nf < 4; nf++) {
            int col = n0b + wn * 32 + nf * 8 + (lane >> 2);
            float v0 = 0.f, v1 = 0.f;
            if (col < N) {
                v0 = ldS(B + (size_t)kOff * ldb + col);
                v1 = ldS(B + (size_t)(kOff + 1) * ldb + col);
            }
            bt[nf] = pack2(v0, v1);
        }
#pragma unroll
        for (int mf = 0; mf < 4; mf++) {
            int r0 = m0 + wm * 64 + mf * 16 + (lane >> 2);
            unsigned at[2];
            at[0] = (r0 < M)     ? ldA2(A + (size_t)r0 * lda + kOff)       : 0u;
            at[1] = (r0 + 8 < M) ? ldA2(A + (size_t)(r0 + 8) * lda + kOff) : 0u;
#pragma unroll
            for (int nf = 0; nf < 4; nf++)
                mma_f16_k8(acc[mf][nf], at, bt[nf]);
        }
    }

    // ---- epilogue
#pragma unroll
    for (int mf = 0; mf < 4; mf++) {
#pragma unroll
        for (int nf = 0; nf < 4; nf++) {
            int row = m0 + wm * 64 + mf * 16 + (lane >> 2);
            int col = n0b + wn * 32 + nf * 8 + ((lane & 3) << 1);
            if (col >= N) continue;
            CT* p = C + (size_t)row * ldc + col;
            float g0 = 0.f, g1 = 0.f, bb0 = 0.f, bb1 = 0.f;
            if (MODE == 2) {
                g0 = epiG[col]; g1 = epiG[col + 1];
                bb0 = epiB[col]; bb1 = epiB[col + 1];
            }
            if (row < M) {
                if (MODE == 1)
                    red2((float*)(void*)p,
                         alpha * acc[mf][nf][0], alpha * acc[mf][nf][1]);
                else if (MODE == 2)
                    store2(p, fmaxf(acc[mf][nf][0] * g0 + bb0, 0.f),
                              fmaxf(acc[mf][nf][1] * g1 + bb1, 0.f));
                else
                    store2(p, alpha * acc[mf][nf][0], alpha * acc[mf][nf][1]);
            }
            if (row + 8 < M) {
                CT* q = p + (size_t)8 * ldc;
                if (MODE == 1)
                    red2((float*)(void*)q,
                         alpha * acc[mf][nf][2], alpha * acc[mf][nf][3]);
                else if (MODE == 2)
                    store2(q, fmaxf(acc[mf][nf][2] * g0 + bb0, 0.f),
                              fmaxf(acc[mf][nf][3] * g1 + bb1, 0.f));
                else
                    store2(q, alpha * acc[mf][nf][2], alpha * acc[mf][nf][3]);
            }
        }
    }
}

// ---------------- SIMT SGEMM (exact fp32) for the weight precompute ------
template <bool ATOMIC>
__global__ void __launch_bounds__(256) sgemm_k(
    const float* __restrict__ A, const float* __restrict__ B,
    float* __restrict__ C, int M, int Ncols, int K,
    int lda, int ldb, int ldc, float alpha, int kChunk)
{
    __shared__ float As[8][128];
    __shared__ float Bs[8][128];

    const int tid = threadIdx.x;
    const int tx = tid & 15;
    const int ty = tid >> 4;
    const int m0 = blockIdx.y * 128;
    const int n0 = blockIdx.x * 128;

    int kBegin = blockIdx.z * kChunk;
    int kEnd = kBegin + kChunk;
    if (kEnd > K) kEnd = K;

    const int aRow = tid >> 1;
    const int aK4  = (tid & 1) << 2;
    const int bRow = tid >> 5;
    const int bCol = (tid & 31) << 2;

    float acc[8][8];
#pragma unroll
    for (int i = 0; i < 8; i++)
#pragma unroll
        for (int j = 0; j < 8; j++) acc[i][j] = 0.f;

    for (int k0 = kBegin; k0 < kEnd; k0 += 8) {
        float4 av = make_float4(0.f, 0.f, 0.f, 0.f);
        if (m0 + aRow < M)
            av = *(const float4*)(A + (size_t)(m0 + aRow) * lda + (k0 + aK4));
        As[aK4 + 0][aRow] = av.x;
        As[aK4 + 1][aRow] = av.y;
        As[aK4 + 2][aRow] = av.z;
        As[aK4 + 3][aRow] = av.w;

        float4 bv = make_float4(0.f, 0.f, 0.f, 0.f);
        if (n0 + bCol < Ncols)
            bv = *(const float4*)(B + (size_t)(k0 + bRow) * ldb + (n0 + bCol));
        *(float4*)&Bs[bRow][bCol] = bv;

        __syncthreads();
#pragma unroll
        for (int kk = 0; kk < 8; kk++) {
            float ar[8], br[8];
#pragma unroll
            for (int i = 0; i < 8; i++) ar[i] = As[kk][ty * 8 + i];
#pragma unroll
            for (int j = 0; j < 8; j++) br[j] = Bs[kk][tx * 8 + j];
#pragma unroll
            for (int i = 0; i < 8; i++)
#pragma unroll
                for (int j = 0; j < 8; j++)
                    acc[i][j] = fmaf(ar[i], br[j], acc[i][j]);
        }
        __syncthreads();
    }

#pragma unroll
    for (int i = 0; i < 8; i++) {
        int m = m0 + ty * 8 + i;
        if (m >= M) continue;
        if (ATOMIC) {
#pragma unroll
            for (int jj = 0; jj < 8; jj += 2) {
                int n = n0 + tx * 8 + jj;
                if (n < Ncols)
                    red2(C + (size_t)m * ldc + n,
                         alpha * acc[i][jj], alpha * acc[i][jj + 1]);
            }
        } else {
#pragma unroll
            for (int jj = 0; jj < 8; jj += 4) {
                int n = n0 + tx * 8 + jj;
                if (n < Ncols) {
                    float4 v = make_float4(alpha * acc[i][jj + 0],
                                           alpha * acc[i][jj + 1],
                                           alpha * acc[i][jj + 2],
                                           alpha * acc[i][jj + 3]);
                    *(float4*)(C + (size_t)m * ldc + n) = v;
                }
            }
        }
    }
}

// ---------------- fp32 -> fp16 bulk convert (n4 = elems/4) ---------------
__global__ void f2h_k(const float* __restrict__ s, __half* __restrict__ d,
                      int n4)
{
    int i = blockIdx.x * 256 + threadIdx.x;
    if (i >= n4) return;
    float4 v = ((const float4*)s)[i];
    uint2 o;
    o.x = pack2(v.x, v.y);
    o.y = pack2(v.z, v.w);
    ((uint2*)d)[i] = o;
}

// ---------------- fc_w permute+convert: fcw2[p*200+nf] = fc_w[nf*198+p] --
__global__ void permfcw_k(const float* __restrict__ fc_w)
{
    int idx = blockIdx.x * 256 + threadIdx.x;   // r*50 + c
    if (idx >= FEATK * 50) return;
    int r = idx / 50;
    int c = idx - r * 50;
    int p  = r / 200;
    int nf = r - p * 200;
    float4 v = *(const float4*)(fc_w + ((size_t)nf * 198 + p) * 200 + c * 4);
    uint2 o;
    o.x = pack2(v.x, v.y);
    o.y = pack2(v.z, v.w);
    *(uint2*)(g_fcwh + (size_t)r * 200 + c * 4) = o;
}

// ---------------- build fused weight comb (200 x 1400, fp16) -------------
__global__ void build_comb_k(const float* __restrict__ E,
                             const float* __restrict__ w_addpos, int ent)
{
    int idx = blockIdx.x * 256 + threadIdx.x;
    if (idx >= 200 * 1400) return;
    int i = idx / 1400;
    int c = idx - i * 1400;
    float v;
    if (c < 1200) {
        int k = c / 200;
        int j = c - k * 200;
        v = 0.5f * E[(size_t)(ent + k) * DD + i] *
            g_U[(size_t)(k * 200 + i) * 200 + j];
    } else {
        v = w_addpos[(size_t)(200 + i) * 200 + (c - 1200)];
    }
    g_combh[(size_t)i * CPITCH + c] = __float2half(v);
}

// ---------------- build Wcat = [0.5*T | w_rel] fp16 (200 x 400) ----------
__global__ void wcat_k(const float* __restrict__ w_rel)
{
    int idx = blockIdx.x * 256 + threadIdx.x;
    if (idx >= 200 * 400) return;
    int i = idx / 400;
    int c = idx - i * 400;
    float v = (c < 200) ? 0.5f * g_T[i * 200 + c]
                        : w_rel[(size_t)i * 200 + (c - 200)];
    g_Wcat[idx] = __float2half(v);
}

// ---------------- conv weight [k][nf] fp16 + epilogue params -------------
__global__ void convprep_k(const float* __restrict__ conv_w,
                           const float* __restrict__ conv_b,
                           const float* __restrict__ bn1_g,
                           const float* __restrict__ bn1_b)
{
    int idx = blockIdx.x * 256 + threadIdx.x;
    if (idx < 32 * 200) {
        int k  = idx / 200;
        int nf = idx - k * 200;
        float v = (k < 21) ? conv_w[nf * 21 + k] : 0.f;
        g_convW[k * 200 + nf] = __float2half(v);
    }
    if (idx < 256) {
        if (idx < 200) {
            float g = bn1_g[idx] * BNS;
            g_epiG[idx] = g;
            g_epiB[idx] = conv_b[idx] * g + bn1_b[idx];
        } else {
            g_epiG[idx] = 0.f;
            g_epiB[idx] = 0.f;
        }
    }
}

// ---------------- hembW[h] = RO[he0,0:200] + sum_k EP[he_k+1, k*200:] ----
__global__ void hembw_k(const int* __restrict__ he, int H)
{
    int t = blockIdx.x * 256 + threadIdx.x;
    int h = t / 50;
    int c = t - h * 50;
    if (h >= H) return;
    const int* row = he + (size_t)h * 7;
    int r = row[0];
    float4 acc = *(const float4*)(g_RO + (size_t)r * 400 + c * 4);
#pragma unroll
    for (int k = 0; k < 6; k++) {
        int e = row[1 + k];
        float4 v = ld4(g_EP + (size_t)e * CPITCH + k * 200 + c * 4);
        acc.x += v.x; acc.y += v.y; acc.z += v.z; acc.w += v.w;
    }
    __half* dst = g_hembW + (size_t)h * 200 + c * 4;
    ((__half2*)dst)[0] = __floats2half2_rn(acc.x, acc.y);
    ((__half2*)dst)[1] = __floats2half2_rn(acc.z, acc.w);
}

// ---------------- per-edge scatter: agg[seg] += hembW[et] + EP[gidx] -----
__global__ void edge_k(const int* __restrict__ ei,
                       const int* __restrict__ et, int NEdge)
{
    int t = blockIdx.x * 256 + threadIdx.x;
    int e = t / 50;
    int c = t - e * 50;
    if (e >= NEdge) return;
    int seg  = ei[e];
    int gidx = ei[NEdge + e];
    int h    = et[e];
    float4 a = ld4(g_hembW + (size_t)h * 200 + c * 4);
    float4 b = ld4(g_EP + (size_t)gidx * CPITCH + 1200 + c * 4);
    float* p = g_agg + (size_t)seg * 200 + c * 4;
    asm volatile("red.global.add.v4.f32 [%0], {%1, %2, %3, %4};"
                 :: "l"(p), "f"(a.x + b.x), "f"(a.y + b.y),
                    "f"(a.z + b.z), "f"(a.w + b.w) : "memory");
}

// ---------------- outE = tanh(bn(0.5*agg + 0.5*E)) -----------------------
__global__ void oute_k(const float* __restrict__ E,
                       const float* __restrict__ g,
                       const float* __restrict__ bb, int Ntot)
{
    int t = blockIdx.x * 256 + threadIdx.x;
    int n = t / 50;
    int c = t - n * 50;
    if (n >= Ntot) return;
    size_t off = (size_t)n * 200 + c * 4;
    float4 e = *(const float4*)(E + off);
    float4 a = *(const float4*)(g_agg + off);
    int d = c * 4;
    float4 o;
    o.x = tanhf(0.5f * (a.x + e.x) * (g[d + 0] * BNS) + bb[d + 0]);
    o.y = tanhf(0.5f * (a.y + e.y) * (g[d + 1] * BNS) + bb[d + 1]);
    o.z = tanhf(0.5f * (a.z + e.z) * (g[d + 2] * BNS) + bb[d + 2]);
    o.w = tanhf(0.5f * (a.w + e.w) * (g[d + 3] * BNS) + bb[d + 3]);
    *(float4*)(g_outE + off) = o;
}

// ---------------- build im2col X rows (fp16): one block per batch b ------
struct IdxPtrs { const int* p[6]; };

__global__ void __launch_bounds__(256) buildX_k(
    const float* __restrict__ ms, const int* __restrict__ r_idx, IdxPtrs ip,
    const float* __restrict__ bn0_g, const float* __restrict__ bn0_b,
    int ent)
{
    __shared__ float xs[7][204];

    int b = blockIdx.x;
    int t = threadIdx.x;

    float g0 = bn0_g[0] * BNS;
    float b0 = bn0_b[0];
    int ri = r_idx[b];

    for (int idx = t; idx < 1400; idx += 256) {
        int i = idx / 200;
        int d = idx - i * 200;
        float v;
        if (i == 0) {
            v = g_RO[(size_t)ri * 400 + 200 + d];
        } else {
            int k = i - 1;
            int eidx = ip.p[k][b];
            v = g_outE[(size_t)eidx * 200 + d] *
                g_outE[(size_t)(ent + k) * 200 + d] * ms[b * 6 + k];
        }
        xs[i][d] = v * g0 + b0;
    }
    __syncthreads();

    // im2col row p: X[(b*198+p)][i*3+q] = xs[i][p+q], pad cols 21..31 = 0
    if (t < 198) {
        int p = t;
        unsigned w[16];
        float x[7][3];
#pragma unroll
        for (int i = 0; i < 7; i++)
#pragma unroll
            for (int q = 0; q < 3; q++) x[i][q] = xs[i][p + q];
        // k = i*3+q pairs: (0,1)(2,3)...(20,pad)
        w[0]  = pack2(x[0][0], x[0][1]);
        w[1]  = pack2(x[0][2], x[1][0]);
        w[2]  = pack2(x[1][1], x[1][2]);
        w[3]  = pack2(x[2][0], x[2][1]);
        w[4]  = pack2(x[2][2], x[3][0]);
        w[5]  = pack2(x[3][1], x[3][2]);
        w[6]  = pack2(x[4][0], x[4][1]);
        w[7]  = pack2(x[4][2], x[5][0]);
        w[8]  = pack2(x[5][1], x[5][2]);
        w[9]  = pack2(x[6][0], x[6][1]);
        w[10] = pack2(x[6][2], 0.f);
#pragma unroll
        for (int q = 11; q < 16; q++) w[q] = 0u;
        uint4* dst = (uint4*)(g_X + ((size_t)b * 198 + p) * 32);
        dst[0] = make_uint4(w[0], w[1], w[2], w[3]);
        dst[1] = make_uint4(w[4], w[5], w[6], w[7]);
        dst[2] = make_uint4(w[8], w[9], w[10], w[11]);
        dst[3] = make_uint4(w[12], w[13], w[14], w[15]);
    }
}

// ---------------- final: relu(bn2(fc + bias)) row-sum -> out[b] ----------
__global__ void final_k(const float* __restrict__ fc_b,
                        const float* __restrict__ g,
                        const float* __restrict__ bb,
                        float* __restrict__ out, int B)
{
    int gt = blockIdx.x * 256 + threadIdx.x;
    int wb = gt >> 5;
    int lane = gt & 31;
    if (wb >= B) return;
    float s = 0.f;
    for (int d = lane; d < 200; d += 32) {
        float v = (g_FCACC[(size_t)wb * 200 + d] + fc_b[d]) * (g[d] * BNS) + bb[d];
        s += fmaxf(v, 0.f);
    }
#pragma unroll
    for (int o = 16; o; o >>= 1) s += __shfl_down_sync(0xffffffffu, s, o);
    if (lane == 0) out[wb] = s;
}

// ---------------- host orchestration ------------------------------------
extern "C" void kernel_launch(void* const* d_in, const int* in_sizes, int n_in,
                              void* d_out, int out_size)
{
    const float* E          = (const float*)d_in[0];
    const float* R          = (const float*)d_in[1];
    const float* w_alle     = (const float*)d_in[2];
    const float* w_addpos   = (const float*)d_in[3];
    const float* w_alleandr = (const float*)d_in[4];
    const float* w_rel      = (const float*)d_in[5];
    const float* conv_w     = (const float*)d_in[6];
    const float* conv_b     = (const float*)d_in[7];
    const float* fc_w       = (const float*)d_in[8];
    const float* fc_b       = (const float*)d_in[9];
    const float* bnmp_g     = (const float*)d_in[10];
    const float* bnmp_b     = (const float*)d_in[11];
    const float* bn0_g      = (const float*)d_in[12];
    const float* bn0_b      = (const float*)d_in[13];
    const float* bn1_g      = (const float*)d_in[14];
    const float* bn1_b      = (const float*)d_in[15];
    const float* bn2_g      = (const float*)d_in[16];
    const float* bn2_b      = (const float*)d_in[17];
    const float* ms         = (const float*)d_in[18];
    const int*   hyperedge  = (const int*)d_in[19];
    const int*   edge_index = (const int*)d_in[20];
    const int*   edge_type  = (const int*)d_in[21];
    const int*   r_idx      = (const int*)d_in[22];
    IdxPtrs ip;
    for (int k = 0; k < 6; k++) ip.p[k] = (const int*)d_in[23 + k];

    const int Ntot  = in_sizes[0] / DD;   // 50006
    const int ent   = Ntot - 6;
    const int NR    = in_sizes[1] / DD;   // 2000
    const int H     = in_sizes[19] / 7;   // 100000
    const int NEdge = in_sizes[21];       // 600000
    const int Bsz   = in_sizes[22];       // 2048

    float *pT, *pU, *pRO, *pAgg, *pFC, *pG, *pB;
    __half *pComb, *pWcat, *pEh, *pRh, *pFcw, *pEP, *pY, *pX, *pCW;
    cudaGetSymbolAddress((void**)&pT,    g_T);
    cudaGetSymbolAddress((void**)&pU,    g_U);
    cudaGetSymbolAddress((void**)&pComb, g_combh);
    cudaGetSymbolAddress((void**)&pWcat, g_Wcat);
    cudaGetSymbolAddress((void**)&pRO,   g_RO);
    cudaGetSymbolAddress((void**)&pEh,   g_Eh);
    cudaGetSymbolAddress((void**)&pRh,   g_Rh);
    cudaGetSymbolAddress((void**)&pFcw,  g_fcwh);
    cudaGetSymbolAddress((void**)&pEP,   g_EP);
    cudaGetSymbolAddress((void**)&pAgg,  g_agg);
    cudaGetSymbolAddress((void**)&pY,    g_Y);
    cudaGetSymbolAddress((void**)&pX,    g_X);
    cudaGetSymbolAddress((void**)&pCW,   g_convW);
    cudaGetSymbolAddress((void**)&pG,    g_epiG);
    cudaGetSymbolAddress((void**)&pB,    g_epiB);
    cudaGetSymbolAddress((void**)&pFC,   g_FCACC);

    cudaMemsetAsync(pT,   0, 200 * 200 * sizeof(float), 0);
    cudaMemsetAsync(pU,   0, 1200 * 200 * sizeof(float), 0);
    cudaMemsetAsync(pAgg, 0, (size_t)Ntot * 200 * sizeof(float), 0);
    cudaMemsetAsync(pFC,  0, (size_t)Bsz * 200 * sizeof(float), 0);

    // fp16 pre-conversions / permutations
    {
        int n4e = Ntot * DD / 4;
        f2h_k<<<(n4e + 255) / 256, 256>>>(E, pEh, n4e);
        permfcw_k<<<(FEATK * 50 + 255) / 256, 256>>>(fc_w);
        int n4r = NR * DD / 4;
        f2h_k<<<(n4r + 255) / 256, 256>>>(R, pRh, n4r);
        convprep_k<<<(32 * 200 + 255) / 256, 256>>>(conv_w, conv_b,
                                                    bn1_g, bn1_b);
    }

    // T = w_alleandr @ w_addpos_top  (exact fp32, split-K)
    sgemm_k<true><<<dim3(2, 2, 13), 256>>>(w_alleandr, w_addpos, pT,
                                           200, 200, 200, 200, 200, 200, 1.f, 16);
    // U = w_alle @ T  (exact fp32)
    sgemm_k<true><<<dim3(2, 10, 5), 256>>>(w_alle, pT, pU,
                                           1200, 200, 200, 200, 200, 200, 1.f, 40);
    // comb (200 x 1400, fp16)
    build_comb_k<<<(200 * 1400 + 255) / 256, 256>>>(E, w_addpos, ent);
    // Wcat = [0.5*T | w_rel] fp16
    wcat_k<<<(200 * 400 + 255) / 256, 256>>>(w_rel);
    // RO = Rh @ Wcat  (fp16 MMA; cols 0..199 = RW, 200..399 = outR)
    hmma_gemm_k<__half, __half, float, 0>
        <<<dim3(4, (NR + 127) / 128, 1), 256>>>(
        pRh, pWcat, pRO, NR, 400, 200, 200, 400, 400, 1.f, 200,
        nullptr, nullptr);
    // EP = Eh @ comb  (fp16 MMA, fp16 out — the big precompute GEMM)
    hmma_gemm_k<__half, __half, __half, 0>
        <<<dim3(11, (Ntot + 127) / 128, 1), 256>>>(
        pEh, pComb, pEP, Ntot, 1400, 200, 200, CPITCH, CPITCH, 1.f, 200,
        nullptr, nullptr);
    // hembW: gather-sum per hyperedge (fp32 accum, fp16 store)
    hembw_k<<<(H * 50 + 255) / 256, 256>>>(hyperedge, H);
    // per-edge scatter (fp16 gathers, fp32 vector RED)
    edge_k<<<(NEdge * 50 + 255) / 256, 256>>>(edge_index, edge_type, NEdge);
    // outE = tanh(bn(0.5*agg + 0.5*E))
    oute_k<<<(Ntot * 50 + 255) / 256, 256>>>(E, bnmp_g, bnmp_b, Ntot);
    // im2col X (bn0 fused)
    buildX_k<<<Bsz, 256>>>(ms, r_idx, ip, bn0_g, bn0_b, ent);
    // Y = relu(conv(X) * g1 + bias)  (fp16 MMA, fused epilogue)
    hmma_gemm_k<__half, __half, __half, 2>
        <<<dim3(2, (Bsz * 198) / 128, 1), 256>>>(
        pX, pCW, pY, Bsz * 198, 200, 32, 32, 200, 200, 1.f, 32, pG, pB);
    // FCACC += Y @ fcwh  (fp16 MMA, split-K 25 x 1584)
    hmma_gemm_k<__half, __half, float, 1>
        <<<dim3(2, (Bsz + 127) / 128, 25), 256>>>(
        pY, pFcw, pFC, Bsz, 200, FEATK, FEATK, 200, 200, 1.f, 1584,
        nullptr, nullptr);
    // out[b] = sum_d relu(bn2(FCACC + fc_b))
    final_k<<<(Bsz * 32 + 255) / 256, 256>>>(fc_b, bn2_g, bn2_b,
                                             (float*)d_out, Bsz);
}

// round 10
// speedup vs baseline: 3.8442x; 1.1341x over previous
#include <cuda_runtime.h>
#include <cuda_fp16.h>
#include <math.h>

// BN scale: 1/sqrt(1 + 1e-5)
#define BNS 0.9999950000374997f

#define DD      200
#define NTOT_MX 50006
#define H_MX    100000
#define NE_MX   600000
#define B_MX    2048
#define NR_MX   2048
#define CPITCH  1408      // EP row pitch (halves)
#define FEATK   39600     // 200 * 198
#define MROWS   (B_MX * 198)   // im2col rows

// ---------------- static device scratch ----------------------------------
__device__ __align__(128) float  g_T[200 * 200];
__device__ __align__(128) float  g_U[1200 * 200];
__device__ __align__(128) __half g_combh[200 * CPITCH];
__device__ __align__(128) __half g_Wcat[200 * 400];   // [0.5*T | w_rel] fp16
__device__ __align__(128) float  g_RO[(size_t)NR_MX * 400]; // [RW | outR]
__device__ __align__(128) __half g_Eh[(size_t)NTOT_MX * 200];
__device__ __align__(128) __half g_Rh[(size_t)NR_MX * 200];
__device__ __align__(128) __half g_fcwh[(size_t)FEATK * 200]; // permuted (p,nf)
__device__ __align__(128) __half g_EP[(size_t)NTOT_MX * CPITCH];
__device__ __align__(128) __half g_hembW[(size_t)H_MX * 200];
__device__ __align__(128) __half g_agg[(size_t)NTOT_MX * 200];   // fp16 RED target
__device__ __align__(128) float  g_outE[(size_t)NTOT_MX * 200];
__device__ __align__(128) __half g_X[(size_t)MROWS * 32];    // im2col, K pad 32
__device__ __align__(128) __half g_convW[32 * 200];          // conv W [k][nf]
__device__ __align__(128) float  g_epiG[256];
__device__ __align__(128) float  g_epiB[256];
__device__ __align__(128) __half g_Y[(size_t)B_MX * FEATK];  // (b)(p*200+nf)
__device__ __align__(128) float  g_FCACC[(size_t)B_MX * 200];

// ---------------- helpers -------------------------------------------------
__device__ __forceinline__ unsigned pack2(float a, float b) {
    __half2 h = __floats2half2_rn(a, b);
    return *(unsigned*)&h;
}
__device__ __forceinline__ void red2(float* p, float x, float y) {
    asm volatile("red.global.add.v2.f32 [%0], {%1, %2};"
                 :: "l"(p), "f"(x), "f"(y) : "memory");
}
__device__ __forceinline__ float4 ld4(const float* p) {
    return *(const float4*)p;
}
__device__ __forceinline__ float4 ld4(const __half* p) {
    uint2 u = *(const uint2*)p;
    __half2 h0 = *(__half2*)&u.x;
    __half2 h1 = *(__half2*)&u.y;
    float2 a = __half22float2(h0);
    float2 b = __half22float2(h1);
    return make_float4(a.x, a.y, b.x, b.y);
}
__device__ __forceinline__ void store2(float* p, float x, float y) {
    *(float2*)p = make_float2(x, y);
}
__device__ __forceinline__ void store2(__half* p, float x, float y) {
    *(__half2*)p = __floats2half2_rn(x, y);
}
__device__ __forceinline__ uint4 ldA8(const float* p) {
    float4 x = *(const float4*)p;
    float4 y = *(const float4*)(p + 4);
    uint4 r;
    r.x = pack2(x.x, x.y); r.y = pack2(x.z, x.w);
    r.z = pack2(y.x, y.y); r.w = pack2(y.z, y.w);
    return r;
}
__device__ __forceinline__ uint4 ldA8(const __half* p) {
    return *(const uint4*)p;
}
__device__ __forceinline__ unsigned ldA2(const float* p) {
    float2 v = *(const float2*)p;
    return pack2(v.x, v.y);
}
__device__ __forceinline__ unsigned ldA2(const __half* p) {
    return *(const unsigned*)p;
}
__device__ __forceinline__ float ldS(const float* p) { return *p; }
__device__ __forceinline__ float ldS(const __half* p) { return __half2float(*p); }

__device__ __forceinline__ void loadBfrag(const float* q, int ldb, unsigned* bS) {
    float2 r0a = *(const float2*)(q);
    float2 r0b = *(const float2*)(q + (size_t)ldb);
    float2 r1a = *(const float2*)(q + (size_t)8 * ldb);
    float2 r1b = *(const float2*)(q + (size_t)9 * ldb);
    bS[0] = pack2(r0a.x, r0b.x);
    bS[1] = pack2(r1a.x, r1b.x);
    bS[2] = pack2(r0a.y, r0b.y);
    bS[3] = pack2(r1a.y, r1b.y);
}
__device__ __forceinline__ void loadBfrag(const __half* q, int ldb, unsigned* bS) {
    __half2 r0a = *(const __half2*)(q);
    __half2 r0b = *(const __half2*)(q + (size_t)ldb);
    __half2 r1a = *(const __half2*)(q + (size_t)8 * ldb);
    __half2 r1b = *(const __half2*)(q + (size_t)9 * ldb);
    __half2 t;
    t = __halves2half2(__low2half(r0a),  __low2half(r0b));  bS[0] = *(unsigned*)&t;
    t = __halves2half2(__low2half(r1a),  __low2half(r1b));  bS[1] = *(unsigned*)&t;
    t = __halves2half2(__high2half(r0a), __high2half(r0b)); bS[2] = *(unsigned*)&t;
    t = __halves2half2(__high2half(r1a), __high2half(r1b)); bS[3] = *(unsigned*)&t;
}

__device__ __forceinline__ void mma_f16_k16(float* c, const unsigned* a,
                                            const unsigned* b) {
    asm volatile(
        "mma.sync.aligned.m16n8k16.row.col.f32.f16.f16.f32 "
        "{%0,%1,%2,%3}, {%4,%5,%6,%7}, {%8,%9}, {%0,%1,%2,%3};"
        : "+f"(c[0]), "+f"(c[1]), "+f"(c[2]), "+f"(c[3])
        : "r"(a[0]), "r"(a[1]), "r"(a[2]), "r"(a[3]), "r"(b[0]), "r"(b[1]));
}
__device__ __forceinline__ void mma_f16_k8(float* c, const unsigned* a,
                                           unsigned b) {
    asm volatile(
        "mma.sync.aligned.m16n8k8.row.col.f32.f16.f16.f32 "
        "{%0,%1,%2,%3}, {%4,%5}, {%6}, {%0,%1,%2,%3};"
        : "+f"(c[0]), "+f"(c[1]), "+f"(c[2]), "+f"(c[3])
        : "r"(a[0]), "r"(a[1]), "r"(b));
}

// =========================================================================
// fp16 tensor-core GEMM (fp32 accum): C = A(MxK,row) @ B(KxN,row)
// MODE 0: C = alpha*acc. MODE 1: red.global += alpha*acc.
// MODE 2: C = relu(acc * epiG[col] + epiB[col])
// Block 128x128, BK=16, 256 threads, warp tile 64x32, m16n8k16.
// Lookahead-2 pipeline: tile it+2 loads to regs while it computes and it+1
// waits in the alternate register set. One __syncthreads per iteration.
// =========================================================================
template <class AT, class BT, class CT, int MODE>
__global__ void __launch_bounds__(256, 2) hmma_gemm_k(
    const AT* __restrict__ A, const BT* __restrict__ B,
    CT* __restrict__ C, int M, int N, int K,
    int lda, int ldb, int ldc, float alpha, int kChunk,
    const float* __restrict__ epiG, const float* __restrict__ epiB)
{
    __shared__ __align__(16) unsigned As[2][1024];
    __shared__ __align__(16) unsigned Bs[2][1056];

    const int tid  = threadIdx.x;
    const int lane = tid & 31;
    const int warp = tid >> 5;
    const int wm = warp >> 2;
    const int wn = warp & 3;
    const int m0 = blockIdx.y * 128;
    const int n0b = blockIdx.x * 128;

    const int kBegin = blockIdx.z * kChunk;
    const int kEnd   = min(kBegin + kChunk, K);
    const int iters  = (kEnd - kBegin) >> 4;
    const bool tail8 = ((kEnd - kBegin) & 8) != 0;

    const int am    = tid >> 1;
    const int khalf = tid & 1;
    const bool aVal = (m0 + am) < M;
    const AT* Ap = A + (size_t)(m0 + am) * lda + kBegin + khalf * 8;
    const int amf  = am >> 4;
    const int ar   = am & 15;
    const int arl  = ar & 7;
    const int aReg = (khalf << 1) | (ar >> 3);

    const int bkp = (tid >> 6) & 3;
    const int bn0 = (tid & 63) << 1;
    const bool bVal = (n0b + bn0) < N;
    const BT* Bp = B + (size_t)(kBegin + 2 * bkp) * ldb + n0b + bn0;
    const int bnf = bn0 >> 3;
    const int bLane0 = (bn0 & 7) * 4 + bkp;

    float acc[4][4][4];
#pragma unroll
    for (int i = 0; i < 4; i++)
#pragma unroll
        for (int j = 0; j < 4; j++)
#pragma unroll
            for (int q = 0; q < 4; q++) acc[i][j][q] = 0.f;

    uint4 aS0, aS1;
    unsigned bS0[4], bS1[4];
    const int lphys = lane ^ ((lane >> 3) & 3);

#define LOADR(IT, AR, BR)                                                    \
    {                                                                        \
        AR = aVal ? ldA8(Ap + ((IT) << 4)) : make_uint4(0u, 0u, 0u, 0u);     \
        if (bVal) loadBfrag(Bp + (size_t)((IT) << 4) * ldb, ldb, BR);        \
        else { BR[0] = BR[1] = BR[2] = BR[3] = 0u; }                         \
    }
#define STORER(BUF, AR, BR)                                                  \
    {                                                                        \
        unsigned aw[4] = {AR.x, AR.y, AR.z, AR.w};                           \
        _Pragma("unroll")                                                    \
        for (int jj = 0; jj < 4; jj++) {                                     \
            int c_   = arl * 4 + jj;                                         \
            int phys = c_ ^ ((c_ >> 3) & 3);                                 \
            As[BUF][amf * 128 + phys * 4 + aReg] = aw[jj];                   \
        }                                                                    \
        Bs[BUF][bnf * 66 + bLane0 * 2 + 0]       = BR[0];                    \
        Bs[BUF][bnf * 66 + bLane0 * 2 + 1]       = BR[1];                    \
        Bs[BUF][bnf * 66 + (bLane0 + 4) * 2 + 0] = BR[2];                    \
        Bs[BUF][bnf * 66 + (bLane0 + 4) * 2 + 1] = BR[3];                    \
    }
#define CONSUME(BUF)                                                         \
    {                                                                        \
        unsigned af[4][4], bf[4][2];                                         \
        _Pragma("unroll")                                                    \
        for (int mf = 0; mf < 4; mf++) {                                     \
            uint4 t = *(const uint4*)&As[BUF][(wm * 4 + mf) * 128 + lphys * 4]; \
            af[mf][0] = t.x; af[mf][1] = t.y; af[mf][2] = t.z; af[mf][3] = t.w; \
        }                                                                    \
        _Pragma("unroll")                                                    \
        for (int nf = 0; nf < 4; nf++) {                                     \
            uint2 t = *(const uint2*)&Bs[BUF][(wn * 4 + nf) * 66 + lane * 2]; \
            bf[nf][0] = t.x; bf[nf][1] = t.y;                                \
        }                                                                    \
        _Pragma("unroll")                                                    \
        for (int mf = 0; mf < 4; mf++)                                       \
            _Pragma("unroll")                                                \
            for (int nf = 0; nf < 4; nf++)                                   \
                mma_f16_k16(acc[mf][nf], af[mf], bf[nf]);                    \
    }

    if (iters > 0) {
        LOADR(0, aS0, bS0);
        STORER(0, aS0, bS0);
        if (iters > 1) LOADR(1, aS1, bS1);
        __syncthreads();
        int it = 0;
        for (;;) {
            if (it + 2 < iters) LOADR(it + 2, aS0, bS0);
            CONSUME(0);
            if (++it >= iters) break;
            STORER(1, aS1, bS1);
            __syncthreads();
            if (it + 2 < iters) LOADR(it + 2, aS1, bS1);
            CONSUME(1);
            if (++it >= iters) break;
            STORER(0, aS0, bS0);
            __syncthreads();
        }
    }
#undef LOADR
#undef STORER
#undef CONSUME

    if (tail8) {
        const int kT = kEnd - 8;
        const int kOff = kT + 2 * (lane & 3);
        unsigned bt[4];
#pragma unroll
        for (int nf = 0; nf < 4; nf++) {
            int col = n0b + wn * 32 + nf * 8 + (lane >> 2);
            float v0 = 0.f, v1 = 0.f;
            if (col < N) {
                v0 = ldS(B + (size_t)kOff * ldb + col);
                v1 = ldS(B + (size_t)(kOff + 1) * ldb + col);
            }
            bt[nf] = pack2(v0, v1);
        }
#pragma unroll
        for (int mf = 0; mf < 4; mf++) {
            int r0 = m0 + wm * 64 + mf * 16 + (lane >> 2);
            unsigned at[2];
            at[0] = (r0 < M)     ? ldA2(A + (size_t)r0 * lda + kOff)       : 0u;
            at[1] = (r0 + 8 < M) ? ldA2(A + (size_t)(r0 + 8) * lda + kOff) : 0u;
#pragma unroll
            for (int nf = 0; nf < 4; nf++)
                mma_f16_k8(acc[mf][nf], at, bt[nf]);
        }
    }

    // ---- epilogue
#pragma unroll
    for (int mf = 0; mf < 4; mf++) {
#pragma unroll
        for (int nf = 0; nf < 4; nf++) {
            int row = m0 + wm * 64 + mf * 16 + (lane >> 2);
            int col = n0b + wn * 32 + nf * 8 + ((lane & 3) << 1);
            if (col >= N) continue;
            CT* p = C + (size_t)row * ldc + col;
            float g0 = 0.f, g1 = 0.f, bb0 = 0.f, bb1 = 0.f;
            if (MODE == 2) {
                g0 = epiG[col]; g1 = epiG[col + 1];
                bb0 = epiB[col]; bb1 = epiB[col + 1];
            }
            if (row < M) {
                if (MODE == 1)
                    red2((float*)(void*)p,
                         alpha * acc[mf][nf][0], alpha * acc[mf][nf][1]);
                else if (MODE == 2)
                    store2(p, fmaxf(acc[mf][nf][0] * g0 + bb0, 0.f),
                              fmaxf(acc[mf][nf][1] * g1 + bb1, 0.f));
                else
                    store2(p, alpha * acc[mf][nf][0], alpha * acc[mf][nf][1]);
            }
            if (row + 8 < M) {
                CT* q = p + (size_t)8 * ldc;
                if (MODE == 1)
                    red2((float*)(void*)q,
                         alpha * acc[mf][nf][2], alpha * acc[mf][nf][3]);
                else if (MODE == 2)
                    store2(q, fmaxf(acc[mf][nf][2] * g0 + bb0, 0.f),
                              fmaxf(acc[mf][nf][3] * g1 + bb1, 0.f));
                else
                    store2(q, alpha * acc[mf][nf][2], alpha * acc[mf][nf][3]);
            }
        }
    }
}

// ---------------- SIMT SGEMM (exact fp32) for the weight precompute ------
template <bool ATOMIC>
__global__ void __launch_bounds__(256) sgemm_k(
    const float* __restrict__ A, const float* __restrict__ B,
    float* __restrict__ C, int M, int Ncols, int K,
    int lda, int ldb, int ldc, float alpha, int kChunk)
{
    __shared__ float As[8][128];
    __shared__ float Bs[8][128];

    const int tid = threadIdx.x;
    const int tx = tid & 15;
    const int ty = tid >> 4;
    const int m0 = blockIdx.y * 128;
    const int n0 = blockIdx.x * 128;

    int kBegin = blockIdx.z * kChunk;
    int kEnd = kBegin + kChunk;
    if (kEnd > K) kEnd = K;

    const int aRow = tid >> 1;
    const int aK4  = (tid & 1) << 2;
    const int bRow = tid >> 5;
    const int bCol = (tid & 31) << 2;

    float acc[8][8];
#pragma unroll
    for (int i = 0; i < 8; i++)
#pragma unroll
        for (int j = 0; j < 8; j++) acc[i][j] = 0.f;

    for (int k0 = kBegin; k0 < kEnd; k0 += 8) {
        float4 av = make_float4(0.f, 0.f, 0.f, 0.f);
        if (m0 + aRow < M)
            av = *(const float4*)(A + (size_t)(m0 + aRow) * lda + (k0 + aK4));
        As[aK4 + 0][aRow] = av.x;
        As[aK4 + 1][aRow] = av.y;
        As[aK4 + 2][aRow] = av.z;
        As[aK4 + 3][aRow] = av.w;

        float4 bv = make_float4(0.f, 0.f, 0.f, 0.f);
        if (n0 + bCol < Ncols)
            bv = *(const float4*)(B + (size_t)(k0 + bRow) * ldb + (n0 + bCol));
        *(float4*)&Bs[bRow][bCol] = bv;

        __syncthreads();
#pragma unroll
        for (int kk = 0; kk < 8; kk++) {
            float ar[8], br[8];
#pragma unroll
            for (int i = 0; i < 8; i++) ar[i] = As[kk][ty * 8 + i];
#pragma unroll
            for (int j = 0; j < 8; j++) br[j] = Bs[kk][tx * 8 + j];
#pragma unroll
            for (int i = 0; i < 8; i++)
#pragma unroll
                for (int j = 0; j < 8; j++)
                    acc[i][j] = fmaf(ar[i], br[j], acc[i][j]);
        }
        __syncthreads();
    }

#pragma unroll
    for (int i = 0; i < 8; i++) {
        int m = m0 + ty * 8 + i;
        if (m >= M) continue;
        if (ATOMIC) {
#pragma unroll
            for (int jj = 0; jj < 8; jj += 2) {
                int n = n0 + tx * 8 + jj;
                if (n < Ncols)
                    red2(C + (size_t)m * ldc + n,
                         alpha * acc[i][jj], alpha * acc[i][jj + 1]);
            }
        } else {
#pragma unroll
            for (int jj = 0; jj < 8; jj += 4) {
                int n = n0 + tx * 8 + jj;
                if (n < Ncols) {
                    float4 v = make_float4(alpha * acc[i][jj + 0],
                                           alpha * acc[i][jj + 1],
                                           alpha * acc[i][jj + 2],
                                           alpha * acc[i][jj + 3]);
                    *(float4*)(C + (size_t)m * ldc + n) = v;
                }
            }
        }
    }
}

// ---------------- fp32 -> fp16 bulk convert (n4 = elems/4) ---------------
__global__ void f2h_k(const float* __restrict__ s, __half* __restrict__ d,
                      int n4)
{
    int i = blockIdx.x * 256 + threadIdx.x;
    if (i >= n4) return;
    float4 v = ((const float4*)s)[i];
    uint2 o;
    o.x = pack2(v.x, v.y);
    o.y = pack2(v.z, v.w);
    ((uint2*)d)[i] = o;
}

// ---------------- fc_w permute+convert: fcw2[p*200+nf] = fc_w[nf*198+p] --
__global__ void permfcw_k(const float* __restrict__ fc_w)
{
    int idx = blockIdx.x * 256 + threadIdx.x;   // r*50 + c
    if (idx >= FEATK * 50) return;
    int r = idx / 50;
    int c = idx - r * 50;
    int p  = r / 200;
    int nf = r - p * 200;
    float4 v = *(const float4*)(fc_w + ((size_t)nf * 198 + p) * 200 + c * 4);
    uint2 o;
    o.x = pack2(v.x, v.y);
    o.y = pack2(v.z, v.w);
    *(uint2*)(g_fcwh + (size_t)r * 200 + c * 4) = o;
}

// ---------------- build fused weight comb (200 x 1400, fp16) -------------
__global__ void build_comb_k(const float* __restrict__ E,
                             const float* __restrict__ w_addpos, int ent)
{
    int idx = blockIdx.x * 256 + threadIdx.x;
    if (idx >= 200 * 1400) return;
    int i = idx / 1400;
    int c = idx - i * 1400;
    float v;
    if (c < 1200) {
        int k = c / 200;
        int j = c - k * 200;
        v = 0.5f * E[(size_t)(ent + k) * DD + i] *
            g_U[(size_t)(k * 200 + i) * 200 + j];
    } else {
        v = w_addpos[(size_t)(200 + i) * 200 + (c - 1200)];
    }
    g_combh[(size_t)i * CPITCH + c] = __float2half(v);
}

// ---------------- build Wcat = [0.5*T | w_rel] fp16 (200 x 400) ----------
__global__ void wcat_k(const float* __restrict__ w_rel)
{
    int idx = blockIdx.x * 256 + threadIdx.x;
    if (idx >= 200 * 400) return;
    int i = idx / 400;
    int c = idx - i * 400;
    float v = (c < 200) ? 0.5f * g_T[i * 200 + c]
                        : w_rel[(size_t)i * 200 + (c - 200)];
    g_Wcat[idx] = __float2half(v);
}

// ---------------- conv weight [k][nf] fp16 + epilogue params -------------
__global__ void convprep_k(const float* __restrict__ conv_w,
                           const float* __restrict__ conv_b,
                           const float* __restrict__ bn1_g,
                           const float* __restrict__ bn1_b)
{
    int idx = blockIdx.x * 256 + threadIdx.x;
    if (idx < 32 * 200) {
        int k  = idx / 200;
        int nf = idx - k * 200;
        float v = (k < 21) ? conv_w[nf * 21 + k] : 0.f;
        g_convW[k * 200 + nf] = __float2half(v);
    }
    if (idx < 256) {
        if (idx < 200) {
            float g = bn1_g[idx] * BNS;
            g_epiG[idx] = g;
            g_epiB[idx] = conv_b[idx] * g + bn1_b[idx];
        } else {
            g_epiG[idx] = 0.f;
            g_epiB[idx] = 0.f;
        }
    }
}

// ---------------- hembW[h] = RO[he0,0:200] + sum_k EP[he_k+1, k*200:] ----
__global__ void hembw_k(const int* __restrict__ he, int H)
{
    int t = blockIdx.x * 256 + threadIdx.x;
    int h = t / 50;
    int c = t - h * 50;
    if (h >= H) return;
    const int* row = he + (size_t)h * 7;
    int r = row[0];
    float4 acc = *(const float4*)(g_RO + (size_t)r * 400 + c * 4);
#pragma unroll
    for (int k = 0; k < 6; k++) {
        int e = row[1 + k];
        float4 v = ld4(g_EP + (size_t)e * CPITCH + k * 200 + c * 4);
        acc.x += v.x; acc.y += v.y; acc.z += v.z; acc.w += v.w;
    }
    __half* dst = g_hembW + (size_t)h * 200 + c * 4;
    ((__half2*)dst)[0] = __floats2half2_rn(acc.x, acc.y);
    ((__half2*)dst)[1] = __floats2half2_rn(acc.z, acc.w);
}

// ---------------- per-edge scatter: agg[seg] += hembW[et] + EP[gidx] -----
// 25 threads/edge, 8 halves each, fp16x2 vector RED.
__global__ void edge_k(const int* __restrict__ ei,
                       const int* __restrict__ et, int NEdge)
{
    int t = blockIdx.x * 256 + threadIdx.x;
    int e = t / 25;
    int c = t - e * 25;
    if (e >= NEdge) return;
    int seg  = ei[e];
    int gidx = ei[NEdge + e];
    int h    = et[e];
    uint4 ua = *(const uint4*)(g_hembW + (size_t)h * 200 + c * 8);
    uint4 ub = *(const uint4*)(g_EP + (size_t)gidx * CPITCH + 1200 + c * 8);
    unsigned r[4];
#pragma unroll
    for (int j = 0; j < 4; j++) {
        __half2 x = ((__half2*)&ua)[j];
        __half2 y = ((__half2*)&ub)[j];
        __half2 s = __hadd2(x, y);
        r[j] = *(unsigned*)&s;
    }
    __half* p = g_agg + (size_t)seg * 200 + c * 8;
    asm volatile("red.global.add.noftz.v4.f16x2 [%0], {%1, %2, %3, %4};"
                 :: "l"(p), "r"(r[0]), "r"(r[1]), "r"(r[2]), "r"(r[3])
                 : "memory");
}

// ---------------- outE = tanh(bn(0.5*agg + 0.5*E)) -----------------------
__global__ void oute_k(const float* __restrict__ E,
                       const float* __restrict__ g,
                       const float* __restrict__ bb, int Ntot)
{
    int t = blockIdx.x * 256 + threadIdx.x;
    int n = t / 50;
    int c = t - n * 50;
    if (n >= Ntot) return;
    size_t off = (size_t)n * 200 + c * 4;
    float4 e = *(const float4*)(E + off);
    float4 a = ld4(g_agg + off);
    int d = c * 4;
    float4 o;
    o.x = tanhf(0.5f * (a.x + e.x) * (g[d + 0] * BNS) + bb[d + 0]);
    o.y = tanhf(0.5f * (a.y + e.y) * (g[d + 1] * BNS) + bb[d + 1]);
    o.z = tanhf(0.5f * (a.z + e.z) * (g[d + 2] * BNS) + bb[d + 2]);
    o.w = tanhf(0.5f * (a.w + e.w) * (g[d + 3] * BNS) + bb[d + 3]);
    *(float4*)(g_outE + off) = o;
}

// ---------------- build im2col X rows (fp16): one block per batch b ------
struct IdxPtrs { const int* p[6]; };

__global__ void __launch_bounds__(256) buildX_k(
    const float* __restrict__ ms, const int* __restrict__ r_idx, IdxPtrs ip,
    const float* __restrict__ bn0_g, const float* __restrict__ bn0_b,
    int ent)
{
    __shared__ float xs[7][204];

    int b = blockIdx.x;
    int t = threadIdx.x;

    float g0 = bn0_g[0] * BNS;
    float b0 = bn0_b[0];
    int ri = r_idx[b];

    for (int idx = t; idx < 1400; idx += 256) {
        int i = idx / 200;
        int d = idx - i * 200;
        float v;
        if (i == 0) {
            v = g_RO[(size_t)ri * 400 + 200 + d];
        } else {
            int k = i - 1;
            int eidx = ip.p[k][b];
            v = g_outE[(size_t)eidx * 200 + d] *
                g_outE[(size_t)(ent + k) * 200 + d] * ms[b * 6 + k];
        }
        xs[i][d] = v * g0 + b0;
    }
    __syncthreads();

    if (t < 198) {
        int p = t;
        unsigned w[16];
        float x[7][3];
#pragma unroll
        for (int i = 0; i < 7; i++)
#pragma unroll
            for (int q = 0; q < 3; q++) x[i][q] = xs[i][p + q];
        w[0]  = pack2(x[0][0], x[0][1]);
        w[1]  = pack2(x[0][2], x[1][0]);
        w[2]  = pack2(x[1][1], x[1][2]);
        w[3]  = pack2(x[2][0], x[2][1]);
        w[4]  = pack2(x[2][2], x[3][0]);
        w[5]  = pack2(x[3][1], x[3][2]);
        w[6]  = pack2(x[4][0], x[4][1]);
        w[7]  = pack2(x[4][2], x[5][0]);
        w[8]  = pack2(x[5][1], x[5][2]);
        w[9]  = pack2(x[6][0], x[6][1]);
        w[10] = pack2(x[6][2], 0.f);
#pragma unroll
        for (int q = 11; q < 16; q++) w[q] = 0u;
        uint4* dst = (uint4*)(g_X + ((size_t)b * 198 + p) * 32);
        dst[0] = make_uint4(w[0], w[1], w[2], w[3]);
        dst[1] = make_uint4(w[4], w[5], w[6], w[7]);
        dst[2] = make_uint4(w[8], w[9], w[10], w[11]);
        dst[3] = make_uint4(w[12], w[13], w[14], w[15]);
    }
}

// ---------------- final: relu(bn2(fc + bias)) row-sum -> out[b] ----------
__global__ void final_k(const float* __restrict__ fc_b,
                        const float* __restrict__ g,
                        const float* __restrict__ bb,
                        float* __restrict__ out, int B)
{
    int gt = blockIdx.x * 256 + threadIdx.x;
    int wb = gt >> 5;
    int lane = gt & 31;
    if (wb >= B) return;
    float s = 0.f;
    for (int d = lane; d < 200; d += 32) {
        float v = (g_FCACC[(size_t)wb * 200 + d] + fc_b[d]) * (g[d] * BNS) + bb[d];
        s += fmaxf(v, 0.f);
    }
#pragma unroll
    for (int o = 16; o; o >>= 1) s += __shfl_down_sync(0xffffffffu, s, o);
    if (lane == 0) out[wb] = s;
}

// ---------------- host orchestration ------------------------------------
extern "C" void kernel_launch(void* const* d_in, const int* in_sizes, int n_in,
                              void* d_out, int out_size)
{
    const float* E          = (const float*)d_in[0];
    const float* R          = (const float*)d_in[1];
    const float* w_alle     = (const float*)d_in[2];
    const float* w_addpos   = (const float*)d_in[3];
    const float* w_alleandr = (const float*)d_in[4];
    const float* w_rel      = (const float*)d_in[5];
    const float* conv_w     = (const float*)d_in[6];
    const float* conv_b     = (const float*)d_in[7];
    const float* fc_w       = (const float*)d_in[8];
    const float* fc_b       = (const float*)d_in[9];
    const float* bnmp_g     = (const float*)d_in[10];
    const float* bnmp_b     = (const float*)d_in[11];
    const float* bn0_g      = (const float*)d_in[12];
    const float* bn0_b      = (const float*)d_in[13];
    const float* bn1_g      = (const float*)d_in[14];
    const float* bn1_b      = (const float*)d_in[15];
    const float* bn2_g      = (const float*)d_in[16];
    const float* bn2_b      = (const float*)d_in[17];
    const float* ms         = (const float*)d_in[18];
    const int*   hyperedge  = (const int*)d_in[19];
    const int*   edge_index = (const int*)d_in[20];
    const int*   edge_type  = (const int*)d_in[21];
    const int*   r_idx      = (const int*)d_in[22];
    IdxPtrs ip;
    for (int k = 0; k < 6; k++) ip.p[k] = (const int*)d_in[23 + k];

    const int Ntot  = in_sizes[0] / DD;   // 50006
    const int ent   = Ntot - 6;
    const int NR    = in_sizes[1] / DD;   // 2000
    const int H     = in_sizes[19] / 7;   // 100000
    const int NEdge = in_sizes[21];       // 600000
    const int Bsz   = in_sizes[22];       // 2048

    float *pT, *pU, *pRO, *pFC, *pG, *pB;
    __half *pComb, *pWcat, *pEh, *pRh, *pFcw, *pEP, *pY, *pX, *pCW, *pAgg;
    cudaGetSymbolAddress((void**)&pT,    g_T);
    cudaGetSymbolAddress((void**)&pU,    g_U);
    cudaGetSymbolAddress((void**)&pComb, g_combh);
    cudaGetSymbolAddress((void**)&pWcat, g_Wcat);
    cudaGetSymbolAddress((void**)&pRO,   g_RO);
    cudaGetSymbolAddress((void**)&pEh,   g_Eh);
    cudaGetSymbolAddress((void**)&pRh,   g_Rh);
    cudaGetSymbolAddress((void**)&pFcw,  g_fcwh);
    cudaGetSymbolAddress((void**)&pEP,   g_EP);
    cudaGetSymbolAddress((void**)&pAgg,  g_agg);
    cudaGetSymbolAddress((void**)&pY,    g_Y);
    cudaGetSymbolAddress((void**)&pX,    g_X);
    cudaGetSymbolAddress((void**)&pCW,   g_convW);
    cudaGetSymbolAddress((void**)&pG,    g_epiG);
    cudaGetSymbolAddress((void**)&pB,    g_epiB);
    cudaGetSymbolAddress((void**)&pFC,   g_FCACC);

    cudaMemsetAsync(pT,   0, 200 * 200 * sizeof(float), 0);
    cudaMemsetAsync(pU,   0, 1200 * 200 * sizeof(float), 0);
    cudaMemsetAsync(pAgg, 0, (size_t)Ntot * 200 * sizeof(__half), 0);
    cudaMemsetAsync(pFC,  0, (size_t)Bsz * 200 * sizeof(float), 0);

    // fp16 pre-conversions / permutations
    {
        int n4e = Ntot * DD / 4;
        f2h_k<<<(n4e + 255) / 256, 256>>>(E, pEh, n4e);
        permfcw_k<<<(FEATK * 50 + 255) / 256, 256>>>(fc_w);
        int n4r = NR * DD / 4;
        f2h_k<<<(n4r + 255) / 256, 256>>>(R, pRh, n4r);
        convprep_k<<<(32 * 200 + 255) / 256, 256>>>(conv_w, conv_b,
                                                    bn1_g, bn1_b);
    }

    // T = w_alleandr @ w_addpos_top  (exact fp32, split-K)
    sgemm_k<true><<<dim3(2, 2, 13), 256>>>(w_alleandr, w_addpos, pT,
                                           200, 200, 200, 200, 200, 200, 1.f, 16);
    // U = w_alle @ T  (exact fp32)
    sgemm_k<true><<<dim3(2, 10, 5), 256>>>(w_alle, pT, pU,
                                           1200, 200, 200, 200, 200, 200, 1.f, 40);
    // comb (200 x 1400, fp16)
    build_comb_k<<<(200 * 1400 + 255) / 256, 256>>>(E, w_addpos, ent);
    // Wcat = [0.5*T | w_rel] fp16
    wcat_k<<<(200 * 400 + 255) / 256, 256>>>(w_rel);
    // RO = Rh @ Wcat  (fp16 MMA; cols 0..199 = RW, 200..399 = outR)
    hmma_gemm_k<__half, __half, float, 0>
        <<<dim3(4, (NR + 127) / 128, 1), 256>>>(
        pRh, pWcat, pRO, NR, 400, 200, 200, 400, 400, 1.f, 200,
        nullptr, nullptr);
    // EP = Eh @ comb  (fp16 MMA, fp16 out — the big precompute GEMM)
    hmma_gemm_k<__half, __half, __half, 0>
        <<<dim3(11, (Ntot + 127) / 128, 1), 256>>>(
        pEh, pComb, pEP, Ntot, 1400, 200, 200, CPITCH, CPITCH, 1.f, 200,
        nullptr, nullptr);
    // hembW: gather-sum per hyperedge (fp32 accum, fp16 store)
    hembw_k<<<(H * 50 + 255) / 256, 256>>>(hyperedge, H);
    // per-edge scatter (fp16 gathers, fp16x2 vector RED)
    edge_k<<<(NEdge * 25 + 255) / 256, 256>>>(edge_index, edge_type, NEdge);
    // outE = tanh(bn(0.5*agg + 0.5*E))
    oute_k<<<(Ntot * 50 + 255) / 256, 256>>>(E, bnmp_g, bnmp_b, Ntot);
    // im2col X (bn0 fused)
    buildX_k<<<Bsz, 256>>>(ms, r_idx, ip, bn0_g, bn0_b, ent);
    // Y = relu(conv(X) * g1 + bias)  (fp16 MMA, fused epilogue)
    hmma_gemm_k<__half, __half, __half, 2>
        <<<dim3(2, (Bsz * 198) / 128, 1), 256>>>(
        pX, pCW, pY, Bsz * 198, 200, 32, 32, 200, 200, 1.f, 32, pG, pB);
    // FCACC += Y @ fcwh  (fp16 MMA, split-K 25 x 1584)
    hmma_gemm_k<__half, __half, float, 1>
        <<<dim3(2, (Bsz + 127) / 128, 25), 256>>>(
        pY, pFcw, pFC, Bsz, 200, FEATK, FEATK, 200, 200, 1.f, 1584,
        nullptr, nullptr);
    // out[b] = sum_d relu(bn2(FCACC + fc_b))
    final_k<<<(Bsz * 32 + 255) / 256, 256>>>(fc_b, bn2_g, bn2_b,
                                             (float*)d_out, Bsz);
}